// round 8
// baseline (speedup 1.0000x reference)
#include <cuda_runtime.h>
#include <cuda_bf16.h>
#include <math.h>
#include <stdint.h>

// Problem dims
#define B_  256
#define T_  128
#define F_  128
#define H_  512
#define NCOMB 2176          // 2048 permuted gate cols + 128 hist cols
#define GRID_MAIN 136       // 4 row-groups x 34 col-tiles
#define THREADS_MAIN 256

// ---------------- persistent device state / scratch ----------------
__device__ float          g_gammah[T_ * B_ * H_];   // [t][b][j]
__device__ float          g_alpha [T_ * B_ * F_];   // [t][b][f]
__device__ __nv_bfloat16  g_hd16hi[B_ * H_];
__device__ __nv_bfloat16  g_hd16lo[B_ * H_];
__device__ __nv_bfloat16  g_cc16hi[B_ * F_];
__device__ __nv_bfloat16  g_cc16lo[B_ * F_];
__device__ __nv_bfloat16  g_m16   [B_ * T_ * F_];
__device__ __nv_bfloat16  g_Bhi   [NCOMB * 768];    // [n'][k], gate cols permuted
__device__ __nv_bfloat16  g_Blo   [NCOMB * 768];
__device__ float          g_biasp [2048];           // permuted b_ih + b_hh
__device__ float          g_xhist [B_ * F_];        // includes hist_b
__device__ float          g_featT [F_ * F_];        // featT[k][f], diag zeroed
__device__ float          g_denom [T_];
__device__ double         g_loss;
// per-producer flags (32B apart): G = end-of-step hdec, H = xhist, C = chain cc
__device__ unsigned       g_flagG[4 * 32 * 8];
__device__ unsigned       g_flagH[4 * 2 * 8];
__device__ unsigned       g_flagC[4 * 32 * 8];

__device__ __forceinline__ float sigf(float v) { return 1.f / (1.f + expf(-v)); }

// ---------------- mma / ldmatrix helpers (base-arch, NOT tcgen05) ----------------
__device__ __forceinline__ void ldsm_x4(uint32_t* r, unsigned addr) {
    asm volatile("ldmatrix.sync.aligned.m8n8.x4.shared.b16 {%0,%1,%2,%3}, [%4];"
                 : "=r"(r[0]), "=r"(r[1]), "=r"(r[2]), "=r"(r[3]) : "r"(addr));
}
__device__ __forceinline__ void mma16816(float* d, const uint32_t* a, const uint32_t* b) {
    asm volatile("mma.sync.aligned.m16n8k16.row.col.f32.bf16.bf16.f32 "
                 "{%0,%1,%2,%3}, {%4,%5,%6,%7}, {%8,%9}, {%0,%1,%2,%3};"
                 : "+f"(d[0]), "+f"(d[1]), "+f"(d[2]), "+f"(d[3])
                 : "r"(a[0]), "r"(a[1]), "r"(a[2]), "r"(a[3]), "r"(b[0]), "r"(b[1]));
}
__device__ __forceinline__ void cpa16(unsigned dst, const void* src) {
    asm volatile("cp.async.cg.shared.global [%0], [%1], 16;" :: "r"(dst), "l"(src) : "memory");
}
__device__ __forceinline__ void cp_commit() { asm volatile("cp.async.commit_group;" ::: "memory"); }
__device__ __forceinline__ void cp_wait0()  { asm volatile("cp.async.wait_group 0;" ::: "memory"); }
__device__ __forceinline__ void cp_wait1()  { asm volatile("cp.async.wait_group 1;" ::: "memory"); }

// ---------------- scoped flag wait / signal ----------------
__device__ __forceinline__ void waitflags(unsigned* base, int n, unsigned target) {
    if (threadIdx.x < n) {
        const volatile unsigned* fl = (const volatile unsigned*)(base + threadIdx.x * 8);
        while (*fl < target) { __nanosleep(32); }
    }
    __syncthreads();
    __threadfence();
}
__device__ __forceinline__ void signalflag(unsigned* fl, unsigned target) {
    __syncthreads();
    if (threadIdx.x == 0) {
        __threadfence();
        atomicExch(fl, target);
    }
}

// ---------------- init ----------------
__global__ void k_init(const float* __restrict__ feat_W) {
    int idx = blockIdx.x * blockDim.x + threadIdx.x;   // 131072 threads
    if (idx < B_ * H_) {
        g_hd16hi[idx] = __float2bfloat16(0.f);
        g_hd16lo[idx] = __float2bfloat16(0.f);
    }
    if (idx == 0) g_loss = 0.0;
    if (idx < 4 * 32 * 8) { g_flagG[idx] = 0u; g_flagC[idx] = 0u; }
    if (idx < 4 * 2 * 8)  g_flagH[idx] = 0u;
    if (idx < F_ * F_) {
        int k = idx >> 7, f = idx & 127;
        g_featT[idx] = (f == k) ? 0.f : feat_W[f * F_ + k];
    }
}

// ---------------- weight split (permuted) + m bf16 + bias ----------------
__global__ void k_prep(const float* __restrict__ W_ih, const float* __restrict__ W_hh,
                       const float* __restrict__ hist_W,
                       const float* __restrict__ b_ih, const float* __restrict__ b_hh,
                       const float* __restrict__ m_all) {
    int stride = gridDim.x * blockDim.x;
    int tid0 = blockIdx.x * blockDim.x + threadIdx.x;
    for (int idx = tid0; idx < NCOMB * 768; idx += stride) {
        int np = idx / 768, k = idx - np * 768;
        float w;
        if (np < 2048) {
            int ct = np >> 6, c = np & 63;
            int n = (c >> 4) * 512 + (ct << 4) + (c & 15);   // gate-interleaved permute
            w = (k < 256) ? W_ih[n * 256 + k] : W_hh[n * 512 + (k - 256)];
        } else {
            int f = np - 2048;
            w = (k < 256) ? 0.f : hist_W[f * 512 + (k - 256)];
        }
        __nv_bfloat16 hi = __float2bfloat16(w);
        g_Bhi[idx] = hi;
        g_Blo[idx] = __float2bfloat16(w - __bfloat162float(hi));
    }
    for (int idx = tid0; idx < B_ * T_ * F_; idx += stride)
        g_m16[idx] = __float2bfloat16(m_all[idx]);
    for (int idx = tid0; idx < 2048; idx += stride) {
        int ct = idx >> 6, c = idx & 63;
        int n = (c >> 4) * 512 + (ct << 4) + (c & 15);
        g_biasp[idx] = b_ih[n] + b_hh[n];
    }
}

// ---------------- denom[t] ----------------
__global__ void k_denom(const float* __restrict__ ev_all) {
    int t = blockIdx.x;
    float s = 0.f;
    for (int i = threadIdx.x; i < B_ * F_; i += 256) {
        int b = i >> 7, f = i & 127;
        s += ev_all[(b * T_ + t) * F_ + f];
    }
    #pragma unroll
    for (int off = 16; off > 0; off >>= 1) s += __shfl_down_sync(0xffffffffu, s, off);
    __shared__ float rs[8];
    int lane = threadIdx.x & 31, w = threadIdx.x >> 5;
    if (lane == 0) rs[w] = s;
    __syncthreads();
    if (threadIdx.x == 0) {
        float tot = 0.f;
        #pragma unroll
        for (int i = 0; i < 8; i++) tot += rs[i];
        g_denom[t] = tot + 1e-8f;
    }
}

// ---------------- precompute GEMMs (fp32 SIMT, parallel over T) ----------------
#define PBM 64
#define PBN 64
#define PBK 32
__global__ __launch_bounds__(256) void k_gammah(const float* __restrict__ d_all,
                                                const float* __restrict__ W,
                                                const float* __restrict__ bias) {
    __shared__ float sA[PBM][PBK + 1];
    __shared__ float sB[PBK][PBN + 1];
    const int rr0 = blockIdx.y * PBM;
    const int bn  = blockIdx.x * PBN;
    const int tid = threadIdx.x;
    const int tr = tid >> 4, tc = tid & 15;
    float acc[4][4] = {};
    for (int k0 = 0; k0 < F_; k0 += PBK) {
        #pragma unroll
        for (int i = tid; i < PBM * PBK; i += 256) {
            int r = i >> 5, kk = i & 31;
            int rr = rr0 + r;
            int b = rr & 255, tt = rr >> 8;
            sA[r][kk] = d_all[(b * T_ + tt) * F_ + k0 + kk];
        }
        #pragma unroll
        for (int i = tid; i < PBK * PBN; i += 256) {
            int nl = i >> 5, kk = i & 31;
            sB[kk][nl] = W[(bn + nl) * F_ + k0 + kk];
        }
        __syncthreads();
        #pragma unroll
        for (int kk = 0; kk < PBK; kk++) {
            float a[4], bb[4];
            #pragma unroll
            for (int i = 0; i < 4; i++) a[i] = sA[tr * 4 + i][kk];
            #pragma unroll
            for (int j = 0; j < 4; j++) bb[j] = sB[kk][tc * 4 + j];
            #pragma unroll
            for (int i = 0; i < 4; i++)
                #pragma unroll
                for (int j = 0; j < 4; j++) acc[i][j] += a[i] * bb[j];
        }
        __syncthreads();
    }
    #pragma unroll
    for (int i = 0; i < 4; i++) {
        int rr = rr0 + tr * 4 + i;
        #pragma unroll
        for (int j = 0; j < 4; j++) {
            int n = bn + tc * 4 + j;
            float v = acc[i][j] + bias[n];
            g_gammah[(size_t)rr * H_ + n] = expf(-fmaxf(v, 0.f));
        }
    }
}

__global__ __launch_bounds__(256) void k_alpha(const float* __restrict__ d_all,
                                               const float* __restrict__ m_all,
                                               const float* __restrict__ tdx_W,
                                               const float* __restrict__ tdx_b,
                                               const float* __restrict__ wc_W,
                                               const float* __restrict__ wc_b) {
    __shared__ float sA[PBM][PBK + 1];
    __shared__ float sB[PBK][PBN + 1];
    const int rr0 = blockIdx.y * PBM;
    const int bn  = blockIdx.x * PBN;
    const int tid = threadIdx.x;
    const int tr = tid >> 4, tc = tid & 15;
    float acc[4][4] = {};
    for (int k0 = 0; k0 < 2 * F_; k0 += PBK) {
        #pragma unroll
        for (int i = tid; i < PBM * PBK; i += 256) {
            int r = i >> 5, kk = i & 31;
            int rr = rr0 + r;
            int b = rr & 255, tt = rr >> 8;
            int k = k0 + kk;
            float v;
            if (k < F_) {
                float dv = d_all[(b * T_ + tt) * F_ + k];
                float gv = dv * tdx_W[k * F_ + k] + tdx_b[k];
                v = expf(-fmaxf(gv, 0.f));
            } else {
                v = m_all[(b * T_ + tt) * F_ + (k - F_)];
            }
            sA[r][kk] = v;
        }
        #pragma unroll
        for (int i = tid; i < PBK * PBN; i += 256) {
            int nl = i >> 5, kk = i & 31;
            sB[kk][nl] = wc_W[(bn + nl) * 2 * F_ + k0 + kk];
        }
        __syncthreads();
        #pragma unroll
        for (int kk = 0; kk < PBK; kk++) {
            float a[4], bb[4];
            #pragma unroll
            for (int i = 0; i < 4; i++) a[i] = sA[tr * 4 + i][kk];
            #pragma unroll
            for (int j = 0; j < 4; j++) bb[j] = sB[kk][tc * 4 + j];
            #pragma unroll
            for (int i = 0; i < 4; i++)
                #pragma unroll
                for (int j = 0; j < 4; j++) acc[i][j] += a[i] * bb[j];
        }
        __syncthreads();
    }
    #pragma unroll
    for (int i = 0; i < 4; i++) {
        int rr = rr0 + tr * 4 + i;
        #pragma unroll
        for (int j = 0; j < 4; j++) {
            int n = bn + tc * 4 + j;
            float s = acc[i][j] + wc_b[n];
            g_alpha[rr * F_ + n] = 1.f / (1.f + expf(-s));
        }
    }
}

// smem byte offsets
#define SM_RED 0                     // 128 B
#define SM_XS  128                   // 2*128 floats = 1024 B
#define SM_A   2048                  // 4 x 8KB A slots (S0..S3)
#define SM_W   (SM_A + 32768)        // weights: WHI 96KB (12 chunks x 8KB) + WLO 96KB
#define SMEM_BYTES (SM_W + 196608)   // 231424

// 64x64x64 bf16 split-MMA chunk: A hi at abase, A lo at abase+8192; B resident
__device__ __forceinline__ void mma_chunk(unsigned abase, unsigned whi, unsigned wlo,
                                          bool has_alo, float acc[4][4],
                                          int lane, int wr, int wcl) {
    const unsigned ahi = abase, alo = abase + 8192u;
    const int arow = wr * 16 + (lane & 15);
    const int aswz = arow & 7;
    #pragma unroll
    for (int ks = 0; ks < 4; ks++) {
        const int achk = ks * 2 + (lane >> 4);
        const unsigned aoff = (unsigned)(arow * 128 + ((achk ^ aswz) << 4));
        uint32_t Ahi[4], Alo[4];
        ldsm_x4(Ahi, ahi + aoff);
        if (has_alo) ldsm_x4(Alo, alo + aoff);
        uint32_t Bhi[8], Blo[8];
        #pragma unroll
        for (int pair = 0; pair < 2; pair++) {
            const int brow = wcl * 32 + pair * 16 + ((lane >> 4) << 3) + (lane & 7);
            const int bchk = ks * 2 + ((lane >> 3) & 1);
            const unsigned boff = (unsigned)(brow * 128 + ((bchk ^ (brow & 7)) << 4));
            ldsm_x4(Bhi + pair * 4, whi + boff);
            ldsm_x4(Blo + pair * 4, wlo + boff);
        }
        #pragma unroll
        for (int nb = 0; nb < 4; nb++) {
            mma16816(acc[nb], Ahi, Bhi + nb * 2);
            if (has_alo) mma16816(acc[nb], Alo, Bhi + nb * 2);
            mma16816(acc[nb], Ahi, Blo + nb * 2);
        }
    }
}

// ---------------- the persistent main kernel ----------------
__global__ __launch_bounds__(THREADS_MAIN, 1) void k_main(
    const float* __restrict__ x_all, const float* __restrict__ m_all,
    const float* __restrict__ tx_all, const float* __restrict__ ev_all,
    const float* __restrict__ hist_b, const float* __restrict__ feat_b,
    float* __restrict__ out) {
    extern __shared__ char smem[];
    const unsigned sm = (unsigned)__cvta_generic_to_shared(smem);
    float* red = (float*)(smem + SM_RED);
    float* xs  = (float*)(smem + SM_XS);
    float* Gs  = (float*)(smem + SM_A + 16384);  // aliases S2,S3 after all P2 mma

    const int tid = threadIdx.x;
    const int lane = tid & 31;
    const int wid = tid >> 5;
    const int wr = wid & 3, wcl = wid >> 2;      // warp 16x32 tile in 64x64
    const int bi = blockIdx.x;
    const int rg = bi / 34, ct = bi % 34;        // row-group, col-tile
    const int row0 = rg * 64;
    const bool is_hist = (ct >= 32);
    const int nb0 = is_hist ? (2048 + (ct - 32) * 64) : (ct * 64);
    const unsigned S0 = sm + SM_A, S1 = S0 + 8192u, S2 = S0 + 16384u, S3 = S0 + 24576u;
    const unsigned WHI = sm + SM_W, WLO = sm + SM_W + 98304u;
    unsigned* myG = g_flagG + (rg * 32 + (is_hist ? 0 : ct)) * 8;
    unsigned* myH = g_flagH + (rg * 2 + (ct - 32)) * 8;
    unsigned* myC = g_flagC + (rg * 32 + ct) * 8;

    // ---- one-time: resident weight load (12 chunks hi + lo) ----
    for (int i = tid; i < 12288; i += THREADS_MAIN) {
        int mat = i / 6144, rem = i - mat * 6144;
        int c = rem >> 9, g = rem & 511, r = g >> 3, p = g & 7;
        unsigned dst = (mat ? WLO : WHI) + (unsigned)(c * 8192 + r * 128 + ((p ^ (r & 7)) << 4));
        const __nv_bfloat16* src = (mat ? g_Blo : g_Bhi) + (size_t)(nb0 + r) * 768 + c * 64 + p * 8;
        cpa16(dst, src);
    }
    cp_commit();
    cp_wait0();
    __syncthreads();

    float cstate[4] = {0.f, 0.f, 0.f, 0.f};

    for (int t = 0; t < T_; t++) {
        if (t > 0) waitflags(g_flagG + rg * 32 * 8, 32, (unsigned)t);

        float acc[4][4] = {};

        // ============ P1: K 256..768, A = hdec (hi/lo), weight chunks 4..11 ============
        {
            for (int i = tid; i < 1024; i += THREADS_MAIN) {
                int mat = i >> 9, g = i & 511, r = g >> 3, p = g & 7;
                unsigned dst = (mat ? S1 : S0) + (unsigned)(r * 128 + ((p ^ (r & 7)) << 4));
                const __nv_bfloat16* src = (mat ? g_hd16lo : g_hd16hi) + (row0 + r) * H_ + p * 8;
                cpa16(dst, src);
            }
            cp_commit();
            for (int c = 0; c < 8; c++) {
                cp_wait0();
                __syncthreads();
                if (c < 7) {
                    int k0 = (c + 1) * 64;
                    unsigned bb = ((c + 1) & 1) ? S2 : S0;
                    for (int i = tid; i < 1024; i += THREADS_MAIN) {
                        int mat = i >> 9, g = i & 511, r = g >> 3, p = g & 7;
                        unsigned dst = bb + (unsigned)(mat * 8192 + r * 128 + ((p ^ (r & 7)) << 4));
                        const __nv_bfloat16* src = (mat ? g_hd16lo : g_hd16hi) + (row0 + r) * H_ + k0 + p * 8;
                        cpa16(dst, src);
                    }
                    cp_commit();
                }
                mma_chunk((c & 1) ? S2 : S0, WHI + (4 + c) * 8192u, WLO + (4 + c) * 8192u,
                          true, acc, lane, wr, wcl);
            }
        }

        if (is_hist) {
            // write x_hist (+hist_b) from register acc, signal H
            const int r0 = wr * 16 + (lane >> 2);
            const int c0g = wcl * 32 + (lane & 3) * 2;
            #pragma unroll
            for (int nb = 0; nb < 4; nb++) {
                #pragma unroll
                for (int q = 0; q < 4; q++) {
                    int r = r0 + ((q >> 1) << 3);
                    int fc = (ct - 32) * 64 + c0g + nb * 8 + (q & 1);
                    __stcg(&g_xhist[(row0 + r) * F_ + fc], acc[nb][q] + hist_b[fc]);
                }
            }
            signalflag(myH, (unsigned)(t + 1));
            continue;   // hist CTA: no chain / P2; next step waits G
        }

        // ---- gate CTA: prestage P2 m-chunks (independent of chain) into S0,S1 ----
        if (t < T_ - 1) {
            for (int i = tid; i < 1024; i += THREADS_MAIN) {
                int mat = i >> 9, g = i & 511, r = g >> 3, p = g & 7;
                unsigned dst = (mat ? S1 : S0) + (unsigned)(r * 128 + ((p ^ (r & 7)) << 4));
                const __nv_bfloat16* src = g_m16 + ((size_t)(row0 + r) * T_ + t) * F_ + mat * 64 + p * 8;
                cpa16(dst, src);
            }
            cp_commit();   // group G1 (m)
        }

        // ============ chain: own 2 rows (row0+2ct, +1) ============
        waitflags(g_flagH + rg * 2 * 8, 2, (unsigned)(t + 1));
        {
            const int rr = tid >> 7, f = tid & 127;
            const int prow = row0 + 2 * ct + rr;
            float xh = __ldcg(&g_xhist[prow * F_ + f]);
            int base = (prow * T_ + t) * F_ + f;
            float mv = m_all[base], xv = x_all[base];
            xs[rr * 128 + f] = mv * xv + (1.f - mv) * xh;
            __syncthreads();
            float z = feat_b[f];
            const float* xrow = xs + rr * 128;
            #pragma unroll 8
            for (int k = 0; k < 128; k++) z += xrow[k] * g_featT[k * F_ + f];
            float al = g_alpha[((size_t)t * B_ + prow) * F_ + f];
            float ch = al * z + (1.f - al) * xh;
            float cc = mv * xv + (1.f - mv) * ch;
            out[base] = cc;
            __nv_bfloat16 hi = __float2bfloat16(cc);
            __stcg(&g_cc16hi[prow * F_ + f], hi);
            __stcg(&g_cc16lo[prow * F_ + f], __float2bfloat16(cc - __bfloat162float(hi)));
            float tg = tx_all[base], evv = ev_all[base];
            float e1 = xh - tg, e2 = z - tg, e3 = ch - tg;
            float l = evv * (e1 * e1 + e2 * e2 + e3 * e3);
            #pragma unroll
            for (int off = 16; off > 0; off >>= 1) l += __shfl_down_sync(0xffffffffu, l, off);
            int ln = tid & 31, w = tid >> 5;
            if (ln == 0) red[w] = l;
            __syncthreads();
            if (tid == 0) {
                float tot = 0.f;
                #pragma unroll
                for (int i = 0; i < 8; i++) tot += red[i];
                atomicAdd(&g_loss, (double)tot / ((double)g_denom[t] * (double)T_));
            }
        }
        if (t == T_ - 1) break;
        signalflag(myC, (unsigned)(t + 1));

        // ============ P2: chunks m2,m3 (prestaged), cc0, cc1; then LSTM ============
        waitflags(g_flagC + rg * 32 * 8, 32, (unsigned)(t + 1));
        {
            // stage cc0 (K 0..63) hi->S2, lo->S3
            for (int i = tid; i < 1024; i += THREADS_MAIN) {
                int mat = i >> 9, g = i & 511, r = g >> 3, p = g & 7;
                unsigned dst = (mat ? S3 : S2) + (unsigned)(r * 128 + ((p ^ (r & 7)) << 4));
                const __nv_bfloat16* src = (mat ? g_cc16lo : g_cc16hi) + (row0 + r) * F_ + p * 8;
                cpa16(dst, src);
            }
            cp_commit();   // group G2 (cc0)
            cp_wait1();    // m (G1) arrived
            __syncthreads();
            mma_chunk(S0, WHI + 2 * 8192u, WLO + 2 * 8192u, false, acc, lane, wr, wcl);  // m2
            mma_chunk(S1, WHI + 3 * 8192u, WLO + 3 * 8192u, false, acc, lane, wr, wcl);  // m3
            __syncthreads();   // m slots free
            // stage cc1 (K 64..127) hi->S0, lo->S1
            for (int i = tid; i < 1024; i += THREADS_MAIN) {
                int mat = i >> 9, g = i & 511, r = g >> 3, p = g & 7;
                unsigned dst = (mat ? S1 : S0) + (unsigned)(r * 128 + ((p ^ (r & 7)) << 4));
                const __nv_bfloat16* src = (mat ? g_cc16lo : g_cc16hi) + (row0 + r) * F_ + 64 + p * 8;
                cpa16(dst, src);
            }
            cp_commit();   // group G3 (cc1)
            cp_wait1();    // cc0 arrived
            __syncthreads();
            mma_chunk(S2, WHI + 0 * 8192u, WLO + 0 * 8192u, true, acc, lane, wr, wcl);   // cc0
            cp_wait0();    // cc1 arrived
            __syncthreads();
            mma_chunk(S0, WHI + 1 * 8192u, WLO + 1 * 8192u, true, acc, lane, wr, wcl);   // cc1
            __syncthreads();
            // epilogue: Gs (at S2,S3) = acc + bias
            {
                const int r0 = wr * 16 + (lane >> 2);
                const int c0g = wcl * 32 + (lane & 3) * 2;
                #pragma unroll
                for (int nb = 0; nb < 4; nb++) {
                    #pragma unroll
                    for (int q = 0; q < 4; q++) {
                        int r = r0 + ((q >> 1) << 3);
                        int c = c0g + nb * 8 + (q & 1);
                        Gs[r * 64 + c] = acc[nb][q] + g_biasp[ct * 64 + c];
                    }
                }
            }
            __syncthreads();
            // LSTM on block-exclusive cells (64 rows x 16 j's), c-state in regs
            #pragma unroll
            for (int u = 0; u < 4; u++) {
                int cell = u * 256 + tid;
                int r = cell >> 4, jj = cell & 15;
                float ig = Gs[r * 64 + jj];
                float fg = Gs[r * 64 + 16 + jj];
                float gg = Gs[r * 64 + 32 + jj];
                float og = Gs[r * 64 + 48 + jj];
                float cn = sigf(fg) * cstate[u] + sigf(ig) * tanhf(gg);
                cstate[u] = cn;
                float h = sigf(og) * tanhf(cn);
                int gidx = (row0 + r) * H_ + ct * 16 + jj;
                float hd = h * g_gammah[(size_t)(t + 1) * B_ * H_ + gidx];
                __nv_bfloat16 hi = __float2bfloat16(hd);
                __stcg(&g_hd16hi[gidx], hi);
                __stcg(&g_hd16lo[gidx], __float2bfloat16(hd - __bfloat162float(hi)));
            }
        }
        signalflag(myG, (unsigned)(t + 1));
    }
}

// ---------------- finalize ----------------
__global__ void k_finish(float* __restrict__ out, int out_size) {
    out[out_size - 1] = (float)g_loss;
}

// ---------------- launch ----------------
extern "C" void kernel_launch(void* const* d_in, const int* in_sizes, int n_in,
                              void* d_out, int out_size) {
    const float* x      = (const float*)d_in[0];
    const float* m      = (const float*)d_in[1];
    const float* d      = (const float*)d_in[2];
    const float* tx     = (const float*)d_in[3];
    const float* ev     = (const float*)d_in[4];
    const float* td_h_W = (const float*)d_in[5];
    const float* td_h_b = (const float*)d_in[6];
    const float* td_x_W = (const float*)d_in[7];
    const float* td_x_b = (const float*)d_in[8];
    const float* hist_W = (const float*)d_in[9];
    const float* hist_b = (const float*)d_in[10];
    const float* feat_W = (const float*)d_in[11];
    const float* feat_b = (const float*)d_in[12];
    const float* wc_W   = (const float*)d_in[13];
    const float* wc_b   = (const float*)d_in[14];
    const float* W_ih   = (const float*)d_in[15];
    const float* W_hh   = (const float*)d_in[16];
    const float* b_ih   = (const float*)d_in[17];
    const float* b_hh   = (const float*)d_in[18];
    float* out = (float*)d_out;

    static int smem_set = 0;
    if (!smem_set) {
        cudaFuncSetAttribute(k_main, cudaFuncAttributeMaxDynamicSharedMemorySize, SMEM_BYTES);
        smem_set = 1;
    }

    k_init<<<512, 256>>>(feat_W);
    k_prep<<<1024, 256>>>(W_ih, W_hh, hist_W, b_ih, b_hh, m);
    k_denom<<<T_, 256>>>(ev);
    k_gammah<<<dim3(H_ / PBN, (T_ * B_) / PBM), 256>>>(d, td_h_W, td_h_b);
    k_alpha<<<dim3(F_ / PBN, (T_ * B_) / PBM), 256>>>(d, m, td_x_W, td_x_b, wc_W, wc_b);
    k_main<<<GRID_MAIN, THREADS_MAIN, SMEM_BYTES>>>(x, m, tx, ev, hist_b, feat_b, out);
    k_finish<<<1, 1>>>(out, out_size);
}

// round 10
// speedup vs baseline: 1.2913x; 1.2913x over previous
#include <cuda_runtime.h>
#include <cuda_bf16.h>
#include <math.h>
#include <stdint.h>

// Problem dims
#define B_  256
#define T_  128
#define F_  128
#define H_  512
#define NGATE 2048          // permuted gate cols
#define GRID_MAIN 128       // 4 row-groups x 32 col-tiles
#define THREADS_MAIN 256

// ---------------- persistent device state / scratch ----------------
__device__ float          g_gammah[T_ * B_ * H_];   // [t][b][j]
__device__ float          g_alpha [T_ * B_ * F_];   // [t][b][f]
__device__ __nv_bfloat16  g_hd16hi[B_ * H_];
__device__ __nv_bfloat16  g_hd16lo[B_ * H_];
__device__ __nv_bfloat16  g_cc16hi[B_ * F_];
__device__ __nv_bfloat16  g_cc16lo[B_ * F_];
__device__ __nv_bfloat16  g_m16   [B_ * T_ * F_];
__device__ __nv_bfloat16  g_Bhi   [NGATE * 768];    // [n'][k], gate cols permuted
__device__ __nv_bfloat16  g_Blo   [NGATE * 768];
__device__ float          g_biasp [2048];           // permuted b_ih + b_hh
__device__ float          g_histT [H_ * F_];        // histT[k][f] fp32
__device__ float          g_featT [F_ * F_];        // featT[k][f], diag zeroed
__device__ float          g_denom [T_];
__device__ double         g_loss;
__device__ unsigned       g_flags [GRID_MAIN * 8];

__device__ __forceinline__ float sigf(float v) { return 1.f / (1.f + expf(-v)); }

// ---------------- mma / ldmatrix helpers (base-arch, NOT tcgen05) ----------------
__device__ __forceinline__ void ldsm_x4(uint32_t* r, unsigned addr) {
    asm volatile("ldmatrix.sync.aligned.m8n8.x4.shared.b16 {%0,%1,%2,%3}, [%4];"
                 : "=r"(r[0]), "=r"(r[1]), "=r"(r[2]), "=r"(r[3]) : "r"(addr));
}
__device__ __forceinline__ void mma16816(float* d, const uint32_t* a, const uint32_t* b) {
    asm volatile("mma.sync.aligned.m16n8k16.row.col.f32.bf16.bf16.f32 "
                 "{%0,%1,%2,%3}, {%4,%5,%6,%7}, {%8,%9}, {%0,%1,%2,%3};"
                 : "+f"(d[0]), "+f"(d[1]), "+f"(d[2]), "+f"(d[3])
                 : "r"(a[0]), "r"(a[1]), "r"(a[2]), "r"(a[3]), "r"(b[0]), "r"(b[1]));
}
__device__ __forceinline__ void cpa16(unsigned dst, const void* src) {
    asm volatile("cp.async.cg.shared.global [%0], [%1], 16;" :: "r"(dst), "l"(src) : "memory");
}
__device__ __forceinline__ void cp_commit() { asm volatile("cp.async.commit_group;" ::: "memory"); }
__device__ __forceinline__ void cp_wait0()  { asm volatile("cp.async.wait_group 0;" ::: "memory"); }
__device__ __forceinline__ void cp_wait1()  { asm volatile("cp.async.wait_group 1;" ::: "memory"); }

// ---------------- init ----------------
__global__ void k_init(const float* __restrict__ feat_W) {
    int idx = blockIdx.x * blockDim.x + threadIdx.x;   // 131072 threads
    if (idx < B_ * H_) {
        g_hd16hi[idx] = __float2bfloat16(0.f);
        g_hd16lo[idx] = __float2bfloat16(0.f);
    }
    if (idx == 0) g_loss = 0.0;
    if (idx < GRID_MAIN * 8) g_flags[idx] = 0u;
    if (idx < F_ * F_) {
        int k = idx >> 7, f = idx & 127;
        g_featT[idx] = (f == k) ? 0.f : feat_W[f * F_ + k];
    }
}

// ---------------- weight split (permuted) + m bf16 + bias + histT ----------------
__global__ void k_prep(const float* __restrict__ W_ih, const float* __restrict__ W_hh,
                       const float* __restrict__ hist_W,
                       const float* __restrict__ b_ih, const float* __restrict__ b_hh,
                       const float* __restrict__ m_all) {
    int stride = gridDim.x * blockDim.x;
    int tid0 = blockIdx.x * blockDim.x + threadIdx.x;
    for (int idx = tid0; idx < NGATE * 768; idx += stride) {
        int np = idx / 768, k = idx - np * 768;
        int ct = np >> 6, c = np & 63;
        int n = (c >> 4) * 512 + (ct << 4) + (c & 15);   // gate-interleaved permute
        float w = (k < 256) ? W_ih[n * 256 + k] : W_hh[n * 512 + (k - 256)];
        __nv_bfloat16 hi = __float2bfloat16(w);
        g_Bhi[idx] = hi;
        g_Blo[idx] = __float2bfloat16(w - __bfloat162float(hi));
    }
    for (int idx = tid0; idx < B_ * T_ * F_; idx += stride)
        g_m16[idx] = __float2bfloat16(m_all[idx]);
    for (int idx = tid0; idx < 2048; idx += stride) {
        int ct = idx >> 6, c = idx & 63;
        int n = (c >> 4) * 512 + (ct << 4) + (c & 15);
        g_biasp[idx] = b_ih[n] + b_hh[n];
    }
    for (int idx = tid0; idx < H_ * F_; idx += stride) {
        int k = idx >> 7, f = idx & 127;
        g_histT[idx] = hist_W[f * H_ + k];
    }
}

// ---------------- denom[t] ----------------
__global__ void k_denom(const float* __restrict__ ev_all) {
    int t = blockIdx.x;
    float s = 0.f;
    for (int i = threadIdx.x; i < B_ * F_; i += 256) {
        int b = i >> 7, f = i & 127;
        s += ev_all[(b * T_ + t) * F_ + f];
    }
    #pragma unroll
    for (int off = 16; off > 0; off >>= 1) s += __shfl_down_sync(0xffffffffu, s, off);
    __shared__ float rs[8];
    int lane = threadIdx.x & 31, w = threadIdx.x >> 5;
    if (lane == 0) rs[w] = s;
    __syncthreads();
    if (threadIdx.x == 0) {
        float tot = 0.f;
        #pragma unroll
        for (int i = 0; i < 8; i++) tot += rs[i];
        g_denom[t] = tot + 1e-8f;
    }
}

// ---------------- precompute GEMMs (fp32 SIMT, parallel over T) ----------------
#define PBM 64
#define PBN 64
#define PBK 32
__global__ __launch_bounds__(256) void k_gammah(const float* __restrict__ d_all,
                                                const float* __restrict__ W,
                                                const float* __restrict__ bias) {
    __shared__ float sA[PBM][PBK + 1];
    __shared__ float sB[PBK][PBN + 1];
    const int rr0 = blockIdx.y * PBM;
    const int bn  = blockIdx.x * PBN;
    const int tid = threadIdx.x;
    const int tr = tid >> 4, tc = tid & 15;
    float acc[4][4] = {};
    for (int k0 = 0; k0 < F_; k0 += PBK) {
        #pragma unroll
        for (int i = tid; i < PBM * PBK; i += 256) {
            int r = i >> 5, kk = i & 31;
            int rr = rr0 + r;
            int b = rr & 255, tt = rr >> 8;
            sA[r][kk] = d_all[(b * T_ + tt) * F_ + k0 + kk];
        }
        #pragma unroll
        for (int i = tid; i < PBK * PBN; i += 256) {
            int nl = i >> 5, kk = i & 31;
            sB[kk][nl] = W[(bn + nl) * F_ + k0 + kk];
        }
        __syncthreads();
        #pragma unroll
        for (int kk = 0; kk < PBK; kk++) {
            float a[4], bb[4];
            #pragma unroll
            for (int i = 0; i < 4; i++) a[i] = sA[tr * 4 + i][kk];
            #pragma unroll
            for (int j = 0; j < 4; j++) bb[j] = sB[kk][tc * 4 + j];
            #pragma unroll
            for (int i = 0; i < 4; i++)
                #pragma unroll
                for (int j = 0; j < 4; j++) acc[i][j] += a[i] * bb[j];
        }
        __syncthreads();
    }
    #pragma unroll
    for (int i = 0; i < 4; i++) {
        int rr = rr0 + tr * 4 + i;
        #pragma unroll
        for (int j = 0; j < 4; j++) {
            int n = bn + tc * 4 + j;
            float v = acc[i][j] + bias[n];
            g_gammah[(size_t)rr * H_ + n] = expf(-fmaxf(v, 0.f));
        }
    }
}

__global__ __launch_bounds__(256) void k_alpha(const float* __restrict__ d_all,
                                               const float* __restrict__ m_all,
                                               const float* __restrict__ tdx_W,
                                               const float* __restrict__ tdx_b,
                                               const float* __restrict__ wc_W,
                                               const float* __restrict__ wc_b) {
    __shared__ float sA[PBM][PBK + 1];
    __shared__ float sB[PBK][PBN + 1];
    const int rr0 = blockIdx.y * PBM;
    const int bn  = blockIdx.x * PBN;
    const int tid = threadIdx.x;
    const int tr = tid >> 4, tc = tid & 15;
    float acc[4][4] = {};
    for (int k0 = 0; k0 < 2 * F_; k0 += PBK) {
        #pragma unroll
        for (int i = tid; i < PBM * PBK; i += 256) {
            int r = i >> 5, kk = i & 31;
            int rr = rr0 + r;
            int b = rr & 255, tt = rr >> 8;
            int k = k0 + kk;
            float v;
            if (k < F_) {
                float dv = d_all[(b * T_ + tt) * F_ + k];
                float gv = dv * tdx_W[k * F_ + k] + tdx_b[k];
                v = expf(-fmaxf(gv, 0.f));
            } else {
                v = m_all[(b * T_ + tt) * F_ + (k - F_)];
            }
            sA[r][kk] = v;
        }
        #pragma unroll
        for (int i = tid; i < PBK * PBN; i += 256) {
            int nl = i >> 5, kk = i & 31;
            sB[kk][nl] = wc_W[(bn + nl) * 2 * F_ + k0 + kk];
        }
        __syncthreads();
        #pragma unroll
        for (int kk = 0; kk < PBK; kk++) {
            float a[4], bb[4];
            #pragma unroll
            for (int i = 0; i < 4; i++) a[i] = sA[tr * 4 + i][kk];
            #pragma unroll
            for (int j = 0; j < 4; j++) bb[j] = sB[kk][tc * 4 + j];
            #pragma unroll
            for (int i = 0; i < 4; i++)
                #pragma unroll
                for (int j = 0; j < 4; j++) acc[i][j] += a[i] * bb[j];
        }
        __syncthreads();
    }
    #pragma unroll
    for (int i = 0; i < 4; i++) {
        int rr = rr0 + tr * 4 + i;
        #pragma unroll
        for (int j = 0; j < 4; j++) {
            int n = bn + tc * 4 + j;
            float s = acc[i][j] + wc_b[n];
            g_alpha[rr * F_ + n] = 1.f / (1.f + expf(-s));
        }
    }
}

// ---------------- distributed-flag grid barrier ----------------
__device__ __forceinline__ void gbar(unsigned target) {
    __syncthreads();
    if (threadIdx.x == 0) {
        __threadfence();
        atomicExch(&g_flags[blockIdx.x * 8], target);
    }
    if (threadIdx.x < GRID_MAIN) {
        const volatile unsigned* fl = (const volatile unsigned*)&g_flags[threadIdx.x * 8];
        while (*fl < target) { __nanosleep(32); }
    }
    __syncthreads();
    __threadfence();
}

// smem byte offsets
#define SM_RED 0                     // 128 B
#define SM_XP  128                   // xhist partials 4*128 floats = 2048 B (xc reuses)
#define SM_A   2176                  // 4 x 8KB A slots (S0..S3), 128B aligned
#define SM_W   (SM_A + 32768)        // weights: WHI 96KB (12 chunks x 8KB) + WLO 96KB
#define SMEM_BYTES (SM_W + 196608)   // 231552

// 64x64x64 bf16 split-MMA chunk: A hi at abase, A lo at abase+8192; B resident
__device__ __forceinline__ void mma_chunk(unsigned abase, unsigned whi, unsigned wlo,
                                          bool has_alo, float acc[4][4],
                                          int lane, int wr, int wcl) {
    const unsigned ahi = abase, alo = abase + 8192u;
    const int arow = wr * 16 + (lane & 15);
    const int aswz = arow & 7;
    #pragma unroll
    for (int ks = 0; ks < 4; ks++) {
        const int achk = ks * 2 + (lane >> 4);
        const unsigned aoff = (unsigned)(arow * 128 + ((achk ^ aswz) << 4));
        uint32_t Ahi[4], Alo[4];
        ldsm_x4(Ahi, ahi + aoff);
        if (has_alo) ldsm_x4(Alo, alo + aoff);
        uint32_t Bhi[8], Blo[8];
        #pragma unroll
        for (int pair = 0; pair < 2; pair++) {
            const int brow = wcl * 32 + pair * 16 + ((lane >> 4) << 3) + (lane & 7);
            const int bchk = ks * 2 + ((lane >> 3) & 1);
            const unsigned boff = (unsigned)(brow * 128 + ((bchk ^ (brow & 7)) << 4));
            ldsm_x4(Bhi + pair * 4, whi + boff);
            ldsm_x4(Blo + pair * 4, wlo + boff);
        }
        #pragma unroll
        for (int nb = 0; nb < 4; nb++) {
            mma16816(acc[nb], Ahi, Bhi + nb * 2);
            if (has_alo) mma16816(acc[nb], Alo, Bhi + nb * 2);
            mma16816(acc[nb], Ahi, Blo + nb * 2);
        }
    }
}

// ---------------- the persistent main kernel ----------------
__global__ __launch_bounds__(THREADS_MAIN, 1) void k_main(
    const float* __restrict__ x_all, const float* __restrict__ m_all,
    const float* __restrict__ tx_all, const float* __restrict__ ev_all,
    const float* __restrict__ hist_b, const float* __restrict__ feat_b,
    float* __restrict__ out) {
    extern __shared__ char smem[];
    const unsigned sm = (unsigned)__cvta_generic_to_shared(smem);
    float* red = (float*)(smem + SM_RED);
    float* xp  = (float*)(smem + SM_XP);          // [kh*2+row][f] partials, then xc
    float* Gs  = (float*)(smem + SM_A + 16384);   // aliases S2,S3 after all P2 mma

    const int tid = threadIdx.x;
    const int lane = tid & 31;
    const int wid = tid >> 5;
    const int wr = wid & 3, wcl = wid >> 2;      // warp 16x32 tile in 64x64
    const int bi = blockIdx.x;
    const int rg = bi >> 5, ct = bi & 31;        // row-group, col-tile
    const int row0 = rg * 64;
    const int nb0 = ct * 64;
    const unsigned S0 = sm + SM_A, S1 = S0 + 8192u, S2 = S0 + 16384u, S3 = S0 + 24576u;
    const unsigned WHI = sm + SM_W, WLO = sm + SM_W + 98304u;
    const char* A0p = smem + SM_A;

    // ---- one-time: resident weight load (12 chunks hi + lo) ----
    for (int i = tid; i < 12288; i += THREADS_MAIN) {
        int mat = i / 6144, rem = i - mat * 6144;
        int c = rem >> 9, g = rem & 511, r = g >> 3, p = g & 7;
        unsigned dst = (mat ? WLO : WHI) + (unsigned)(c * 8192 + r * 128 + ((p ^ (r & 7)) << 4));
        const __nv_bfloat16* src = (mat ? g_Blo : g_Bhi) + (size_t)(nb0 + r) * 768 + c * 64 + p * 8;
        cpa16(dst, src);
    }
    cp_commit();
    cp_wait0();
    __syncthreads();

    float cstate[4] = {0.f, 0.f, 0.f, 0.f};
    // xhist side-compute mapping: kh = which K half of chunk, xf = feature col
    const int kh = tid >> 7, xf = tid & 127;
    const int xr0 = 2 * ct, xr1 = 2 * ct + 1;    // local rows in the 64-row tile

    for (int t = 0; t < T_; t++) {
        float acc[4][4] = {};
        float xa0 = 0.f, xa1 = 0.f;

        // ============ P1: K 256..768, A = hdec (hi/lo), weight chunks 4..11 ============
        {
            for (int i = tid; i < 1024; i += THREADS_MAIN) {
                int mat = i >> 9, g = i & 511, r = g >> 3, p = g & 7;
                unsigned dst = (mat ? S1 : S0) + (unsigned)(r * 128 + ((p ^ (r & 7)) << 4));
                const __nv_bfloat16* src = (mat ? g_hd16lo : g_hd16hi) + (row0 + r) * H_ + p * 8;
                cpa16(dst, src);
            }
            cp_commit();
            for (int c = 0; c < 8; c++) {
                cp_wait0();
                __syncthreads();
                if (c < 7) {
                    int k0 = (c + 1) * 64;
                    unsigned bb = ((c + 1) & 1) ? S2 : S0;
                    for (int i = tid; i < 1024; i += THREADS_MAIN) {
                        int mat = i >> 9, g = i & 511, r = g >> 3, p = g & 7;
                        unsigned dst = bb + (unsigned)(mat * 8192 + r * 128 + ((p ^ (r & 7)) << 4));
                        const __nv_bfloat16* src = (mat ? g_hd16lo : g_hd16hi) + (row0 + r) * H_ + k0 + p * 8;
                        cpa16(dst, src);
                    }
                    cp_commit();
                }
                mma_chunk((c & 1) ? S2 : S0, WHI + (4 + c) * 8192u, WLO + (4 + c) * 8192u,
                          true, acc, lane, wr, wcl);
                // xhist side-compute: rows 2ct, 2ct+1 from the same staged tile
                {
                    const char* hip = A0p + ((c & 1) ? 16384 : 0);
                    const char* lop = hip + 8192;
                    const float* wp = g_histT + (c * 64) * F_ + xf;
                    #pragma unroll
                    for (int p4 = 0; p4 < 4; p4++) {
                        int p = kh * 4 + p4;
                        uint4 h0 = *(const uint4*)(hip + xr0 * 128 + ((p ^ (xr0 & 7)) << 4));
                        uint4 l0 = *(const uint4*)(lop + xr0 * 128 + ((p ^ (xr0 & 7)) << 4));
                        uint4 h1 = *(const uint4*)(hip + xr1 * 128 + ((p ^ (xr1 & 7)) << 4));
                        uint4 l1 = *(const uint4*)(lop + xr1 * 128 + ((p ^ (xr1 & 7)) << 4));
                        const uint32_t* H0 = &h0.x; const uint32_t* L0 = &l0.x;
                        const uint32_t* H1 = &h1.x; const uint32_t* L1 = &l1.x;
                        #pragma unroll
                        for (int q = 0; q < 4; q++) {
                            __nv_bfloat162 hh0 = *(const __nv_bfloat162*)&H0[q];
                            __nv_bfloat162 ll0 = *(const __nv_bfloat162*)&L0[q];
                            __nv_bfloat162 hh1 = *(const __nv_bfloat162*)&H1[q];
                            __nv_bfloat162 ll1 = *(const __nv_bfloat162*)&L1[q];
                            float w0 = wp[(p * 8 + q * 2) * F_];
                            float w1 = wp[(p * 8 + q * 2 + 1) * F_];
                            xa0 += (__low2float(hh0)  + __low2float(ll0))  * w0;
                            xa0 += (__high2float(hh0) + __high2float(ll0)) * w1;
                            xa1 += (__low2float(hh1)  + __low2float(ll1))  * w0;
                            xa1 += (__high2float(hh1) + __high2float(ll1)) * w1;
                        }
                    }
                }
            }
        }

        // ---- prestage P2 m-chunks into freed S0/S1 (no cross-CTA dependency) ----
        if (t < T_ - 1) {
            for (int i = tid; i < 1024; i += THREADS_MAIN) {
                int mat = i >> 9, g = i & 511, r = g >> 3, p = g & 7;
                unsigned dst = (mat ? S1 : S0) + (unsigned)(r * 128 + ((p ^ (r & 7)) << 4));
                const __nv_bfloat16* src = g_m16 + ((size_t)(row0 + r) * T_ + t) * F_ + mat * 64 + p * 8;
                cpa16(dst, src);
            }
            cp_commit();   // group G1 (m)
        }

        // ---- publish xhist partials, then fully local chain ----
        xp[(kh * 2 + 0) * F_ + xf] = xa0;
        xp[(kh * 2 + 1) * F_ + xf] = xa1;
        __syncthreads();
        {
            const int rr = tid >> 7, f = tid & 127;
            const int prow = row0 + 2 * ct + rr;
            float xh = xp[rr * F_ + f] + xp[(2 + rr) * F_ + f] + hist_b[f];
            int base = (prow * T_ + t) * F_ + f;
            float mv = m_all[base], xv = x_all[base];
            float xc = mv * xv + (1.f - mv) * xh;
            __syncthreads();                 // xp fully read -> safe to overwrite
            xp[rr * F_ + f] = xc;            // xc lives in xp region
            __syncthreads();
            float z = feat_b[f];
            const float* xrow = xp + rr * F_;
            #pragma unroll 8
            for (int k = 0; k < 128; k++) z += xrow[k] * g_featT[k * F_ + f];
            float al = g_alpha[((size_t)t * B_ + prow) * F_ + f];
            float ch = al * z + (1.f - al) * xh;
            float cc = mv * xv + (1.f - mv) * ch;
            out[base] = cc;
            __nv_bfloat16 hi = __float2bfloat16(cc);
            __stcg(&g_cc16hi[prow * F_ + f], hi);
            __stcg(&g_cc16lo[prow * F_ + f], __float2bfloat16(cc - __bfloat162float(hi)));
            float tg = tx_all[base], evv = ev_all[base];
            float e1 = xh - tg, e2 = z - tg, e3 = ch - tg;
            float l = evv * (e1 * e1 + e2 * e2 + e3 * e3);
            #pragma unroll
            for (int off = 16; off > 0; off >>= 1) l += __shfl_down_sync(0xffffffffu, l, off);
            int ln = tid & 31, w = tid >> 5;
            if (ln == 0) red[w] = l;
            __syncthreads();
            if (tid == 0) {
                float tot = 0.f;
                #pragma unroll
                for (int i = 0; i < 8; i++) tot += red[i];
                atomicAdd(&g_loss, (double)tot / ((double)g_denom[t] * (double)T_));
            }
        }
        if (t == T_ - 1) break;
        gbar((unsigned)(2 * t + 1));   // cc visible across row-group

        // ============ P2: m2,m3 (prestaged), cc0, cc1; then LSTM ============
        {
            // stage cc0 (K 0..63) hi->S2, lo->S3
            for (int i = tid; i < 1024; i += THREADS_MAIN) {
                int mat = i >> 9, g = i & 511, r = g >> 3, p = g & 7;
                unsigned dst = (mat ? S3 : S2) + (unsigned)(r * 128 + ((p ^ (r & 7)) << 4));
                const __nv_bfloat16* src = (mat ? g_cc16lo : g_cc16hi) + (row0 + r) * F_ + p * 8;
                cpa16(dst, src);
            }
            cp_commit();   // G2 (cc0)
            cp_wait1();    // G1 (m) arrived
            __syncthreads();
            mma_chunk(S0, WHI + 2 * 8192u, WLO + 2 * 8192u, false, acc, lane, wr, wcl);  // m2
            mma_chunk(S1, WHI + 3 * 8192u, WLO + 3 * 8192u, false, acc, lane, wr, wcl);  // m3
            __syncthreads();   // m slots free
            // stage cc1 (K 64..127) hi->S0, lo->S1
            for (int i = tid; i < 1024; i += THREADS_MAIN) {
                int mat = i >> 9, g = i & 511, r = g >> 3, p = g & 7;
                unsigned dst = (mat ? S1 : S0) + (unsigned)(r * 128 + ((p ^ (r & 7)) << 4));
                const __nv_bfloat16* src = (mat ? g_cc16lo : g_cc16hi) + (row0 + r) * F_ + 64 + p * 8;
                cpa16(dst, src);
            }
            cp_commit();   // G3 (cc1)
            cp_wait1();    // cc0 arrived
            __syncthreads();
            mma_chunk(S2, WHI + 0 * 8192u, WLO + 0 * 8192u, true, acc, lane, wr, wcl);   // cc0
            cp_wait0();    // cc1 arrived
            __syncthreads();
            mma_chunk(S0, WHI + 1 * 8192u, WLO + 1 * 8192u, true, acc, lane, wr, wcl);   // cc1
            // epilogue: Gs (at S2,S3) = acc + bias
            {
                const int r0 = wr * 16 + (lane >> 2);
                const int c0g = wcl * 32 + (lane & 3) * 2;
                #pragma unroll
                for (int nb = 0; nb < 4; nb++) {
                    #pragma unroll
                    for (int q = 0; q < 4; q++) {
                        int r = r0 + ((q >> 1) << 3);
                        int c = c0g + nb * 8 + (q & 1);
                        Gs[r * 64 + c] = acc[nb][q] + g_biasp[ct * 64 + c];
                    }
                }
            }
            __syncthreads();
            // LSTM on block-exclusive cells (64 rows x 16 j's), c-state in regs
            #pragma unroll
            for (int u = 0; u < 4; u++) {
                int cell = u * 256 + tid;
                int r = cell >> 4, jj = cell & 15;
                float ig = Gs[r * 64 + jj];
                float fg = Gs[r * 64 + 16 + jj];
                float gg = Gs[r * 64 + 32 + jj];
                float og = Gs[r * 64 + 48 + jj];
                float cn = sigf(fg) * cstate[u] + sigf(ig) * tanhf(gg);
                cstate[u] = cn;
                float h = sigf(og) * tanhf(cn);
                int gidx = (row0 + r) * H_ + ct * 16 + jj;
                float hd = h * g_gammah[(size_t)(t + 1) * B_ * H_ + gidx];
                __nv_bfloat16 hi = __float2bfloat16(hd);
                __stcg(&g_hd16hi[gidx], hi);
                __stcg(&g_hd16lo[gidx], __float2bfloat16(hd - __bfloat162float(hi)));
            }
        }
        gbar((unsigned)(2 * t + 2));   // hdec visible across row-group
    }
}

// ---------------- finalize ----------------
__global__ void k_finish(float* __restrict__ out, int out_size) {
    out[out_size - 1] = (float)g_loss;
}

// ---------------- launch ----------------
extern "C" void kernel_launch(void* const* d_in, const int* in_sizes, int n_in,
                              void* d_out, int out_size) {
    const float* x      = (const float*)d_in[0];
    const float* m      = (const float*)d_in[1];
    const float* d      = (const float*)d_in[2];
    const float* tx     = (const float*)d_in[3];
    const float* ev     = (const float*)d_in[4];
    const float* td_h_W = (const float*)d_in[5];
    const float* td_h_b = (const float*)d_in[6];
    const float* td_x_W = (const float*)d_in[7];
    const float* td_x_b = (const float*)d_in[8];
    const float* hist_W = (const float*)d_in[9];
    const float* hist_b = (const float*)d_in[10];
    const float* feat_W = (const float*)d_in[11];
    const float* feat_b = (const float*)d_in[12];
    const float* wc_W   = (const float*)d_in[13];
    const float* wc_b   = (const float*)d_in[14];
    const float* W_ih   = (const float*)d_in[15];
    const float* W_hh   = (const float*)d_in[16];
    const float* b_ih   = (const float*)d_in[17];
    const float* b_hh   = (const float*)d_in[18];
    float* out = (float*)d_out;

    static int smem_set = 0;
    if (!smem_set) {
        cudaFuncSetAttribute(k_main, cudaFuncAttributeMaxDynamicSharedMemorySize, SMEM_BYTES);
        smem_set = 1;
    }

    k_init<<<512, 256>>>(feat_W);
    k_prep<<<1024, 256>>>(W_ih, W_hh, hist_W, b_ih, b_hh, m);
    k_denom<<<T_, 256>>>(ev);
    k_gammah<<<dim3(H_ / PBN, (T_ * B_) / PBM), 256>>>(d, td_h_W, td_h_b);
    k_alpha<<<dim3(F_ / PBN, (T_ * B_) / PBM), 256>>>(d, m, td_x_W, td_x_b, wc_W, wc_b);
    k_main<<<GRID_MAIN, THREADS_MAIN, SMEM_BYTES>>>(x, m, tx, ev, hist_b, feat_b, out);
    k_finish<<<1, 1>>>(out, out_size);
}

// round 15
// speedup vs baseline: 1.4243x; 1.1030x over previous
#include <cuda_runtime.h>
#include <cuda_bf16.h>
#include <math.h>
#include <stdint.h>

// Problem dims
#define B_  256
#define T_  128
#define F_  128
#define H_  512
#define NCOMB 2176          // 2048 permuted gate cols + 128 hist cols
#define GRID_MAIN 136       // 4 row-groups x 34 col-tiles
#define THREADS_MAIN 256

// ---------------- persistent device state / scratch ----------------
__device__ float          g_gammah[T_ * B_ * H_];   // [t][b][j]
__device__ float          g_alpha [T_ * B_ * F_];   // [t][b][f]
__device__ __nv_bfloat16  g_hd16hi[B_ * H_];
__device__ __nv_bfloat16  g_hd16lo[B_ * H_];
__device__ __nv_bfloat16  g_cc16hi[B_ * F_];
__device__ __nv_bfloat16  g_cc16lo[B_ * F_];
__device__ __nv_bfloat16  g_m16   [B_ * T_ * F_];
__device__ __nv_bfloat16  g_Bhi   [NCOMB * 768];    // [n'][k], gate cols permuted
__device__ __nv_bfloat16  g_Blo   [NCOMB * 768];
__device__ float          g_biasp [2048];           // permuted b_ih + b_hh
__device__ float          g_xhist [B_ * F_];        // includes hist_b
__device__ float          g_featT [F_ * F_];        // featT[k][f], diag zeroed
__device__ float          g_denom [T_];
__device__ double         g_loss;
__device__ unsigned       g_flags [GRID_MAIN * 8];

__device__ __forceinline__ float sigf(float v) { return 1.f / (1.f + expf(-v)); }

// ---------------- mma / ldmatrix helpers (base-arch, NOT tcgen05) ----------------
__device__ __forceinline__ void ldsm_x4(uint32_t* r, unsigned addr) {
    asm volatile("ldmatrix.sync.aligned.m8n8.x4.shared.b16 {%0,%1,%2,%3}, [%4];"
                 : "=r"(r[0]), "=r"(r[1]), "=r"(r[2]), "=r"(r[3]) : "r"(addr));
}
__device__ __forceinline__ void mma16816(float* d, const uint32_t* a, const uint32_t* b) {
    asm volatile("mma.sync.aligned.m16n8k16.row.col.f32.bf16.bf16.f32 "
                 "{%0,%1,%2,%3}, {%4,%5,%6,%7}, {%8,%9}, {%0,%1,%2,%3};"
                 : "+f"(d[0]), "+f"(d[1]), "+f"(d[2]), "+f"(d[3])
                 : "r"(a[0]), "r"(a[1]), "r"(a[2]), "r"(a[3]), "r"(b[0]), "r"(b[1]));
}
__device__ __forceinline__ void cpa16(unsigned dst, const void* src) {
    asm volatile("cp.async.cg.shared.global [%0], [%1], 16;" :: "r"(dst), "l"(src) : "memory");
}
__device__ __forceinline__ void cp_commit() { asm volatile("cp.async.commit_group;" ::: "memory"); }
__device__ __forceinline__ void cp_wait0()  { asm volatile("cp.async.wait_group 0;" ::: "memory"); }
__device__ __forceinline__ void cp_wait1()  { asm volatile("cp.async.wait_group 1;" ::: "memory"); }

// ---------------- init ----------------
__global__ void k_init(const float* __restrict__ feat_W) {
    int idx = blockIdx.x * blockDim.x + threadIdx.x;   // 131072 threads
    if (idx < B_ * H_) {
        g_hd16hi[idx] = __float2bfloat16(0.f);
        g_hd16lo[idx] = __float2bfloat16(0.f);
    }
    if (idx == 0) g_loss = 0.0;
    if (idx < GRID_MAIN * 8) g_flags[idx] = 0u;
    if (idx < F_ * F_) {
        int k = idx >> 7, f = idx & 127;
        g_featT[idx] = (f == k) ? 0.f : feat_W[f * F_ + k];
    }
}

// ---------------- weight split (permuted) + m bf16 + bias ----------------
__global__ void k_prep(const float* __restrict__ W_ih, const float* __restrict__ W_hh,
                       const float* __restrict__ hist_W,
                       const float* __restrict__ b_ih, const float* __restrict__ b_hh,
                       const float* __restrict__ m_all) {
    int stride = gridDim.x * blockDim.x;
    int tid0 = blockIdx.x * blockDim.x + threadIdx.x;
    for (int idx = tid0; idx < NCOMB * 768; idx += stride) {
        int np = idx / 768, k = idx - np * 768;
        float w;
        if (np < 2048) {
            int ct = np >> 6, c = np & 63;
            int n = (c >> 4) * 512 + (ct << 4) + (c & 15);   // gate-interleaved permute
            w = (k < 256) ? W_ih[n * 256 + k] : W_hh[n * 512 + (k - 256)];
        } else {
            int f = np - 2048;
            w = (k < 256) ? 0.f : hist_W[f * 512 + (k - 256)];
        }
        __nv_bfloat16 hi = __float2bfloat16(w);
        g_Bhi[idx] = hi;
        g_Blo[idx] = __float2bfloat16(w - __bfloat162float(hi));
    }
    for (int idx = tid0; idx < B_ * T_ * F_; idx += stride)
        g_m16[idx] = __float2bfloat16(m_all[idx]);
    for (int idx = tid0; idx < 2048; idx += stride) {
        int ct = idx >> 6, c = idx & 63;
        int n = (c >> 4) * 512 + (ct << 4) + (c & 15);
        g_biasp[idx] = b_ih[n] + b_hh[n];
    }
}

// ---------------- denom[t] ----------------
__global__ void k_denom(const float* __restrict__ ev_all) {
    int t = blockIdx.x;
    float s = 0.f;
    for (int i = threadIdx.x; i < B_ * F_; i += 256) {
        int b = i >> 7, f = i & 127;
        s += ev_all[(b * T_ + t) * F_ + f];
    }
    #pragma unroll
    for (int off = 16; off > 0; off >>= 1) s += __shfl_down_sync(0xffffffffu, s, off);
    __shared__ float rs[8];
    int lane = threadIdx.x & 31, w = threadIdx.x >> 5;
    if (lane == 0) rs[w] = s;
    __syncthreads();
    if (threadIdx.x == 0) {
        float tot = 0.f;
        #pragma unroll
        for (int i = 0; i < 8; i++) tot += rs[i];
        g_denom[t] = tot + 1e-8f;
    }
}

// ---------------- precompute GEMMs (fp32 SIMT, vectorized smem) ----------------
#define PBM 64
#define PBN 64
#define PBK 32
__global__ __launch_bounds__(256) void k_gammah(const float* __restrict__ d_all,
                                                const float* __restrict__ W,
                                                const float* __restrict__ bias) {
    __shared__ float sAT[PBK][PBM + 4];   // transposed: [kk][r], 16B-aligned rows
    __shared__ float sB [PBK][PBN + 4];
    const int rr0 = blockIdx.y * PBM;
    const int bn  = blockIdx.x * PBN;
    const int tid = threadIdx.x;
    const int tr = tid >> 4, tc = tid & 15;
    float acc[4][4] = {};
    for (int k0 = 0; k0 < F_; k0 += PBK) {
        #pragma unroll
        for (int i = tid; i < PBM * PBK; i += 256) {
            int r = i >> 5, kk = i & 31;
            int rr = rr0 + r;
            int b = rr & 255, tt = rr >> 8;
            sAT[kk][r] = d_all[(b * T_ + tt) * F_ + k0 + kk];
        }
        #pragma unroll
        for (int i = tid; i < PBK * PBN; i += 256) {
            int nl = i >> 5, kk = i & 31;
            sB[kk][nl] = W[(bn + nl) * F_ + k0 + kk];
        }
        __syncthreads();
        #pragma unroll
        for (int kk = 0; kk < PBK; kk++) {
            float4 a4 = *(const float4*)&sAT[kk][tr * 4];
            float4 b4 = *(const float4*)&sB[kk][tc * 4];
            const float* a = &a4.x;
            const float* bb = &b4.x;
            #pragma unroll
            for (int i = 0; i < 4; i++)
                #pragma unroll
                for (int j = 0; j < 4; j++) acc[i][j] += a[i] * bb[j];
        }
        __syncthreads();
    }
    #pragma unroll
    for (int i = 0; i < 4; i++) {
        int rr = rr0 + tr * 4 + i;
        #pragma unroll
        for (int j = 0; j < 4; j++) {
            int n = bn + tc * 4 + j;
            float v = acc[i][j] + bias[n];
            g_gammah[(size_t)rr * H_ + n] = expf(-fmaxf(v, 0.f));
        }
    }
}

__global__ __launch_bounds__(256) void k_alpha(const float* __restrict__ d_all,
                                               const float* __restrict__ m_all,
                                               const float* __restrict__ tdx_W,
                                               const float* __restrict__ tdx_b,
                                               const float* __restrict__ wc_W,
                                               const float* __restrict__ wc_b) {
    __shared__ float sAT[PBK][PBM + 4];
    __shared__ float sB [PBK][PBN + 4];
    const int rr0 = blockIdx.y * PBM;
    const int bn  = blockIdx.x * PBN;
    const int tid = threadIdx.x;
    const int tr = tid >> 4, tc = tid & 15;
    float acc[4][4] = {};
    for (int k0 = 0; k0 < 2 * F_; k0 += PBK) {
        #pragma unroll
        for (int i = tid; i < PBM * PBK; i += 256) {
            int r = i >> 5, kk = i & 31;
            int rr = rr0 + r;
            int b = rr & 255, tt = rr >> 8;
            int k = k0 + kk;
            float v;
            if (k < F_) {
                float dv = d_all[(b * T_ + tt) * F_ + k];
                float gv = dv * tdx_W[k * F_ + k] + tdx_b[k];
                v = expf(-fmaxf(gv, 0.f));
            } else {
                v = m_all[(b * T_ + tt) * F_ + (k - F_)];
            }
            sAT[kk][r] = v;
        }
        #pragma unroll
        for (int i = tid; i < PBK * PBN; i += 256) {
            int nl = i >> 5, kk = i & 31;
            sB[kk][nl] = wc_W[(bn + nl) * 2 * F_ + k0 + kk];
        }
        __syncthreads();
        #pragma unroll
        for (int kk = 0; kk < PBK; kk++) {
            float4 a4 = *(const float4*)&sAT[kk][tr * 4];
            float4 b4 = *(const float4*)&sB[kk][tc * 4];
            const float* a = &a4.x;
            const float* bb = &b4.x;
            #pragma unroll
            for (int i = 0; i < 4; i++)
                #pragma unroll
                for (int j = 0; j < 4; j++) acc[i][j] += a[i] * bb[j];
        }
        __syncthreads();
    }
    #pragma unroll
    for (int i = 0; i < 4; i++) {
        int rr = rr0 + tr * 4 + i;
        #pragma unroll
        for (int j = 0; j < 4; j++) {
            int n = bn + tc * 4 + j;
            float s = acc[i][j] + wc_b[n];
            g_alpha[rr * F_ + n] = 1.f / (1.f + expf(-s));
        }
    }
}

// ---------------- distributed-flag grid barrier ----------------
__device__ __forceinline__ void gbar(unsigned target) {
    __syncthreads();
    if (threadIdx.x == 0) {
        __threadfence();
        atomicExch(&g_flags[blockIdx.x * 8], target);
    }
    if (threadIdx.x < GRID_MAIN) {
        const volatile unsigned* fl = (const volatile unsigned*)&g_flags[threadIdx.x * 8];
        while (*fl < target) { __nanosleep(32); }
    }
    __syncthreads();
    __threadfence();
}

// smem byte offsets
#define SM_RED 0                     // 128 B
#define SM_XS  128                   // 2*128 floats = 1024 B
#define SM_A   2048                  // 4 x 8KB A slots (S0..S3)
#define SM_W   (SM_A + 32768)        // weights: WHI 96KB (12 chunks x 8KB) + WLO 96KB
#define SMEM_BYTES (SM_W + 196608)   // 231424

// 64x64x64 bf16 split-MMA chunk: A hi at abase, A lo at abase+8192; B resident
__device__ __forceinline__ void mma_chunk(unsigned abase, unsigned whi, unsigned wlo,
                                          bool has_alo, float acc[4][4],
                                          int lane, int wr, int wcl) {
    const unsigned ahi = abase, alo = abase + 8192u;
    const int arow = wr * 16 + (lane & 15);
    const int aswz = arow & 7;
    #pragma unroll
    for (int ks = 0; ks < 4; ks++) {
        const int achk = ks * 2 + (lane >> 4);
        const unsigned aoff = (unsigned)(arow * 128 + ((achk ^ aswz) << 4));
        uint32_t Ahi[4], Alo[4];
        ldsm_x4(Ahi, ahi + aoff);
        if (has_alo) ldsm_x4(Alo, alo + aoff);
        uint32_t Bhi[8], Blo[8];
        #pragma unroll
        for (int pair = 0; pair < 2; pair++) {
            const int brow = wcl * 32 + pair * 16 + ((lane >> 4) << 3) + (lane & 7);
            const int bchk = ks * 2 + ((lane >> 3) & 1);
            const unsigned boff = (unsigned)(brow * 128 + ((bchk ^ (brow & 7)) << 4));
            ldsm_x4(Bhi + pair * 4, whi + boff);
            ldsm_x4(Blo + pair * 4, wlo + boff);
        }
        #pragma unroll
        for (int nb = 0; nb < 4; nb++) {
            mma16816(acc[nb], Ahi, Bhi + nb * 2);
            if (has_alo) mma16816(acc[nb], Alo, Bhi + nb * 2);
            mma16816(acc[nb], Ahi, Blo + nb * 2);
        }
    }
}

// ---------------- the persistent main kernel ----------------
__global__ __launch_bounds__(THREADS_MAIN, 1) void k_main(
    const float* __restrict__ x_all, const float* __restrict__ m_all,
    const float* __restrict__ tx_all, const float* __restrict__ ev_all,
    const float* __restrict__ hist_b, const float* __restrict__ feat_b,
    float* __restrict__ out) {
    extern __shared__ char smem[];
    const unsigned sm = (unsigned)__cvta_generic_to_shared(smem);
    float* red = (float*)(smem + SM_RED);
    float* xs  = (float*)(smem + SM_XS);
    float* Gs  = (float*)(smem + SM_A + 16384);   // aliases S2,S3 after all P2 mma

    const int tid = threadIdx.x;
    const int lane = tid & 31;
    const int wid = tid >> 5;
    const int wr = wid & 3, wcl = wid >> 2;      // warp 16x32 tile in 64x64
    const int bi = blockIdx.x;
    const int rg = bi / 34, ct = bi % 34;        // row-group, col-tile
    const int row0 = rg * 64;
    const bool is_hist = (ct >= 32);
    const int nb0 = is_hist ? (2048 + (ct - 32) * 64) : (ct * 64);
    const unsigned S0 = sm + SM_A, S1 = S0 + 8192u, S2 = S0 + 16384u, S3 = S0 + 24576u;
    const unsigned WHI = sm + SM_W, WLO = sm + SM_W + 98304u;

    // ---- one-time: resident weight load (12 chunks hi + lo) ----
    for (int i = tid; i < 12288; i += THREADS_MAIN) {
        int mat = i / 6144, rem = i - mat * 6144;
        int c = rem >> 9, g = rem & 511, r = g >> 3, p = g & 7;
        unsigned dst = (mat ? WLO : WHI) + (unsigned)(c * 8192 + r * 128 + ((p ^ (r & 7)) << 4));
        const __nv_bfloat16* src = (mat ? g_Blo : g_Bhi) + (size_t)(nb0 + r) * 768 + c * 64 + p * 8;
        cpa16(dst, src);
    }
    cp_commit();
    cp_wait0();
    __syncthreads();

    float cstate[4] = {0.f, 0.f, 0.f, 0.f};
    unsigned bar = 0;

    for (int t = 0; t < T_; t++) {
        float acc[4][4] = {};

        // ============ P1: K 256..768, A = hdec (hi/lo), weight chunks 4..11 ============
        {
            for (int i = tid; i < 1024; i += THREADS_MAIN) {
                int mat = i >> 9, g = i & 511, r = g >> 3, p = g & 7;
                unsigned dst = (mat ? S1 : S0) + (unsigned)(r * 128 + ((p ^ (r & 7)) << 4));
                const __nv_bfloat16* src = (mat ? g_hd16lo : g_hd16hi) + (row0 + r) * H_ + p * 8;
                cpa16(dst, src);
            }
            cp_commit();
            for (int c = 0; c < 8; c++) {
                cp_wait0();
                __syncthreads();
                if (c < 7) {
                    int k0 = (c + 1) * 64;
                    unsigned bb = ((c + 1) & 1) ? S2 : S0;
                    for (int i = tid; i < 1024; i += THREADS_MAIN) {
                        int mat = i >> 9, g = i & 511, r = g >> 3, p = g & 7;
                        unsigned dst = bb + (unsigned)(mat * 8192 + r * 128 + ((p ^ (r & 7)) << 4));
                        const __nv_bfloat16* src = (mat ? g_hd16lo : g_hd16hi) + (row0 + r) * H_ + k0 + p * 8;
                        cpa16(dst, src);
                    }
                    cp_commit();
                }
                mma_chunk((c & 1) ? S2 : S0, WHI + (4 + c) * 8192u, WLO + (4 + c) * 8192u,
                          true, acc, lane, wr, wcl);
            }
        }

        if (is_hist) {
            // write x_hist (+hist_b) from register acc
            const int r0 = wr * 16 + (lane >> 2);
            const int c0g = wcl * 32 + (lane & 3) * 2;
            #pragma unroll
            for (int nb = 0; nb < 4; nb++) {
                #pragma unroll
                for (int q = 0; q < 4; q++) {
                    int r = r0 + ((q >> 1) << 3);
                    int fc = (ct - 32) * 64 + c0g + nb * 8 + (q & 1);
                    __stcg(&g_xhist[(row0 + r) * F_ + fc], acc[nb][q] + hist_b[fc]);
                }
            }
        } else if (t < T_ - 1) {
            // prestage P2 m-chunks into freed S0/S1 (P1's last mma read S2/S3 only)
            for (int i = tid; i < 1024; i += THREADS_MAIN) {
                int mat = i >> 9, g = i & 511, r = g >> 3, p = g & 7;
                unsigned dst = (mat ? S1 : S0) + (unsigned)(r * 128 + ((p ^ (r & 7)) << 4));
                const __nv_bfloat16* src = g_m16 + ((size_t)(row0 + r) * T_ + t) * F_ + mat * 64 + p * 8;
                cpa16(dst, src);
            }
            cp_commit();   // group G1 (m)
        }
        gbar(++bar);

        // ============ chain: rows 2bi, 2bi+1 (CTAs 0..127) ============
        if (bi < 128) {
            const int rr = tid >> 7, f = tid & 127;
            const int prow = bi * 2 + rr;
            float xh = __ldcg(&g_xhist[prow * F_ + f]);
            int base = (prow * T_ + t) * F_ + f;
            float mv = m_all[base], xv = x_all[base];
            xs[rr * 128 + f] = mv * xv + (1.f - mv) * xh;
            __syncthreads();
            float z = feat_b[f];
            const float* xrow = xs + rr * 128;
            #pragma unroll 8
            for (int k = 0; k < 128; k++) z += xrow[k] * g_featT[k * F_ + f];
            float al = g_alpha[((size_t)t * B_ + prow) * F_ + f];
            float ch = al * z + (1.f - al) * xh;
            float cc = mv * xv + (1.f - mv) * ch;
            out[base] = cc;
            __nv_bfloat16 hi = __float2bfloat16(cc);
            __stcg(&g_cc16hi[prow * F_ + f], hi);
            __stcg(&g_cc16lo[prow * F_ + f], __float2bfloat16(cc - __bfloat162float(hi)));
            float tg = tx_all[base], evv = ev_all[base];
            float e1 = xh - tg, e2 = z - tg, e3 = ch - tg;
            float l = evv * (e1 * e1 + e2 * e2 + e3 * e3);
            #pragma unroll
            for (int off = 16; off > 0; off >>= 1) l += __shfl_down_sync(0xffffffffu, l, off);
            int ln = tid & 31, w = tid >> 5;
            if (ln == 0) red[w] = l;
            __syncthreads();
            if (tid == 0) {
                float tot = 0.f;
                #pragma unroll
                for (int i = 0; i < 8; i++) tot += red[i];
                atomicAdd(&g_loss, (double)tot / ((double)g_denom[t] * (double)T_));
            }
        }
        if (t == T_ - 1) break;
        gbar(++bar);

        // ============ P2: m2,m3 (prestaged), cc0, cc1; then LSTM ============
        if (!is_hist) {
            // stage cc0 (K 0..63) hi->S2, lo->S3
            for (int i = tid; i < 1024; i += THREADS_MAIN) {
                int mat = i >> 9, g = i & 511, r = g >> 3, p = g & 7;
                unsigned dst = (mat ? S3 : S2) + (unsigned)(r * 128 + ((p ^ (r & 7)) << 4));
                const __nv_bfloat16* src = (mat ? g_cc16lo : g_cc16hi) + (row0 + r) * F_ + p * 8;
                cpa16(dst, src);
            }
            cp_commit();   // G2 (cc0)
            cp_wait1();    // G1 (m) arrived
            __syncthreads();
            mma_chunk(S0, WHI + 2 * 8192u, WLO + 2 * 8192u, false, acc, lane, wr, wcl);  // m2
            mma_chunk(S1, WHI + 3 * 8192u, WLO + 3 * 8192u, false, acc, lane, wr, wcl);  // m3
            __syncthreads();   // m slots free
            // stage cc1 (K 64..127) hi->S0, lo->S1
            for (int i = tid; i < 1024; i += THREADS_MAIN) {
                int mat = i >> 9, g = i & 511, r = g >> 3, p = g & 7;
                unsigned dst = (mat ? S1 : S0) + (unsigned)(r * 128 + ((p ^ (r & 7)) << 4));
                const __nv_bfloat16* src = (mat ? g_cc16lo : g_cc16hi) + (row0 + r) * F_ + 64 + p * 8;
                cpa16(dst, src);
            }
            cp_commit();   // G3 (cc1)
            cp_wait1();    // cc0 arrived
            __syncthreads();
            mma_chunk(S2, WHI + 0 * 8192u, WLO + 0 * 8192u, true, acc, lane, wr, wcl);   // cc0
            cp_wait0();    // cc1 arrived
            __syncthreads();
            mma_chunk(S0, WHI + 1 * 8192u, WLO + 1 * 8192u, true, acc, lane, wr, wcl);   // cc1
            // epilogue: Gs (at S2,S3) = acc + bias
            {
                const int r0 = wr * 16 + (lane >> 2);
                const int c0g = wcl * 32 + (lane & 3) * 2;
                #pragma unroll
                for (int nb = 0; nb < 4; nb++) {
                    #pragma unroll
                    for (int q = 0; q < 4; q++) {
                        int r = r0 + ((q >> 1) << 3);
                        int c = c0g + nb * 8 + (q & 1);
                        Gs[r * 64 + c] = acc[nb][q] + g_biasp[ct * 64 + c];
                    }
                }
            }
            __syncthreads();
            // LSTM on block-exclusive cells (64 rows x 16 j's), c-state in regs
            #pragma unroll
            for (int u = 0; u < 4; u++) {
                int cell = u * 256 + tid;
                int r = cell >> 4, jj = cell & 15;
                float ig = Gs[r * 64 + jj];
                float fg = Gs[r * 64 + 16 + jj];
                float gg = Gs[r * 64 + 32 + jj];
                float og = Gs[r * 64 + 48 + jj];
                float cn = sigf(fg) * cstate[u] + sigf(ig) * tanhf(gg);
                cstate[u] = cn;
                float h = sigf(og) * tanhf(cn);
                int gidx = (row0 + r) * H_ + ct * 16 + jj;
                float hd = h * g_gammah[(size_t)(t + 1) * B_ * H_ + gidx];
                __nv_bfloat16 hi = __float2bfloat16(hd);
                __stcg(&g_hd16hi[gidx], hi);
                __stcg(&g_hd16lo[gidx], __float2bfloat16(hd - __bfloat162float(hi)));
            }
        }
        gbar(++bar);
    }
}

// ---------------- finalize ----------------
__global__ void k_finish(float* __restrict__ out, int out_size) {
    out[out_size - 1] = (float)g_loss;
}

// ---------------- launch ----------------
extern "C" void kernel_launch(void* const* d_in, const int* in_sizes, int n_in,
                              void* d_out, int out_size) {
    const float* x      = (const float*)d_in[0];
    const float* m      = (const float*)d_in[1];
    const float* d      = (const float*)d_in[2];
    const float* tx     = (const float*)d_in[3];
    const float* ev     = (const float*)d_in[4];
    const float* td_h_W = (const float*)d_in[5];
    const float* td_h_b = (const float*)d_in[6];
    const float* td_x_W = (const float*)d_in[7];
    const float* td_x_b = (const float*)d_in[8];
    const float* hist_W = (const float*)d_in[9];
    const float* hist_b = (const float*)d_in[10];
    const float* feat_W = (const float*)d_in[11];
    const float* feat_b = (const float*)d_in[12];
    const float* wc_W   = (const float*)d_in[13];
    const float* wc_b   = (const float*)d_in[14];
    const float* W_ih   = (const float*)d_in[15];
    const float* W_hh   = (const float*)d_in[16];
    const float* b_ih   = (const float*)d_in[17];
    const float* b_hh   = (const float*)d_in[18];
    float* out = (float*)d_out;

    static int smem_set = 0;
    if (!smem_set) {
        cudaFuncSetAttribute(k_main, cudaFuncAttributeMaxDynamicSharedMemorySize, SMEM_BYTES);
        smem_set = 1;
    }

    k_init<<<512, 256>>>(feat_W);
    k_prep<<<1024, 256>>>(W_ih, W_hh, hist_W, b_ih, b_hh, m);
    k_denom<<<T_, 256>>>(ev);
    k_gammah<<<dim3(H_ / PBN, (T_ * B_) / PBM), 256>>>(d, td_h_W, td_h_b);
    k_alpha<<<dim3(F_ / PBN, (T_ * B_) / PBM), 256>>>(d, m, td_x_W, td_x_b, wc_W, wc_b);
    k_main<<<GRID_MAIN, THREADS_MAIN, SMEM_BYTES>>>(x, m, tx, ev, hist_b, feat_b, out);
    k_finish<<<1, 1>>>(out, out_size);
}

// round 16
// speedup vs baseline: 1.5421x; 1.0827x over previous
#include <cuda_runtime.h>
#include <cuda_fp16.h>
#include <math.h>
#include <stdint.h>

// Problem dims
#define B_  256
#define T_  128
#define F_  128
#define H_  512
#define NCOMB 2176          // 2048 permuted gate cols + 128 hist cols
#define GRID_MAIN 136       // 4 row-groups x 34 col-tiles
#define THREADS_MAIN 256

// ---------------- persistent device state / scratch ----------------
__device__ float   g_gammah[T_ * B_ * H_];   // [t][b][j]
__device__ float   g_alpha [T_ * B_ * F_];   // [t][b][f]
__device__ __half  g_hd16  [B_ * H_];        // fp16 single (|hd|<1)
__device__ __half  g_cc16  [B_ * F_];
__device__ __half  g_m16   [B_ * T_ * F_];
__device__ __half  g_Bhi   [NCOMB * 768];    // [n'][k], gate cols permuted, fp16 hi
__device__ __half  g_Blo   [NCOMB * 768];    // fp16 residual
__device__ float   g_biasp [2048];           // permuted b_ih + b_hh
__device__ float   g_xhist [B_ * F_];        // includes hist_b
__device__ float   g_featT [F_ * F_];        // featT[k][f], diag zeroed
__device__ float   g_denom [T_];
__device__ double  g_loss;
__device__ unsigned g_flags[GRID_MAIN * 8];

__device__ __forceinline__ float sigf(float v) { return 1.f / (1.f + expf(-v)); }

// ---------------- mma / ldmatrix helpers (base-arch, NOT tcgen05) ----------------
__device__ __forceinline__ void ldsm_x4(uint32_t* r, unsigned addr) {
    asm volatile("ldmatrix.sync.aligned.m8n8.x4.shared.b16 {%0,%1,%2,%3}, [%4];"
                 : "=r"(r[0]), "=r"(r[1]), "=r"(r[2]), "=r"(r[3]) : "r"(addr));
}
__device__ __forceinline__ void mma16816(float* d, const uint32_t* a, const uint32_t* b) {
    asm volatile("mma.sync.aligned.m16n8k16.row.col.f32.f16.f16.f32 "
                 "{%0,%1,%2,%3}, {%4,%5,%6,%7}, {%8,%9}, {%0,%1,%2,%3};"
                 : "+f"(d[0]), "+f"(d[1]), "+f"(d[2]), "+f"(d[3])
                 : "r"(a[0]), "r"(a[1]), "r"(a[2]), "r"(a[3]), "r"(b[0]), "r"(b[1]));
}
__device__ __forceinline__ void cpa16(unsigned dst, const void* src) {
    asm volatile("cp.async.cg.shared.global [%0], [%1], 16;" :: "r"(dst), "l"(src) : "memory");
}
__device__ __forceinline__ void cp_commit() { asm volatile("cp.async.commit_group;" ::: "memory"); }
__device__ __forceinline__ void cp_wait0()  { asm volatile("cp.async.wait_group 0;" ::: "memory"); }
__device__ __forceinline__ void cp_wait1()  { asm volatile("cp.async.wait_group 1;" ::: "memory"); }

// ---------------- init ----------------
__global__ void k_init(const float* __restrict__ feat_W) {
    int idx = blockIdx.x * blockDim.x + threadIdx.x;   // 131072 threads
    if (idx < B_ * H_) g_hd16[idx] = __float2half(0.f);
    if (idx == 0) g_loss = 0.0;
    if (idx < GRID_MAIN * 8) g_flags[idx] = 0u;
    if (idx < F_ * F_) {
        int k = idx >> 7, f = idx & 127;
        g_featT[idx] = (f == k) ? 0.f : feat_W[f * F_ + k];
    }
}

// ---------------- weight split (permuted, fp16 hi/lo) + m fp16 + bias ----------------
__global__ void k_prep(const float* __restrict__ W_ih, const float* __restrict__ W_hh,
                       const float* __restrict__ hist_W,
                       const float* __restrict__ b_ih, const float* __restrict__ b_hh,
                       const float* __restrict__ m_all) {
    int stride = gridDim.x * blockDim.x;
    int tid0 = blockIdx.x * blockDim.x + threadIdx.x;
    for (int idx = tid0; idx < NCOMB * 768; idx += stride) {
        int np = idx / 768, k = idx - np * 768;
        float w;
        if (np < 2048) {
            int ct = np >> 6, c = np & 63;
            int n = (c >> 4) * 512 + (ct << 4) + (c & 15);   // gate-interleaved permute
            w = (k < 256) ? W_ih[n * 256 + k] : W_hh[n * 512 + (k - 256)];
        } else {
            int f = np - 2048;
            w = (k < 256) ? 0.f : hist_W[f * 512 + (k - 256)];
        }
        __half hi = __float2half(w);
        g_Bhi[idx] = hi;
        g_Blo[idx] = __float2half(w - __half2float(hi));
    }
    for (int idx = tid0; idx < B_ * T_ * F_; idx += stride)
        g_m16[idx] = __float2half(m_all[idx]);
    for (int idx = tid0; idx < 2048; idx += stride) {
        int ct = idx >> 6, c = idx & 63;
        int n = (c >> 4) * 512 + (ct << 4) + (c & 15);
        g_biasp[idx] = b_ih[n] + b_hh[n];
    }
}

// ---------------- denom[t] ----------------
__global__ void k_denom(const float* __restrict__ ev_all) {
    int t = blockIdx.x;
    float s = 0.f;
    for (int i = threadIdx.x; i < B_ * F_; i += 256) {
        int b = i >> 7, f = i & 127;
        s += ev_all[(b * T_ + t) * F_ + f];
    }
    #pragma unroll
    for (int off = 16; off > 0; off >>= 1) s += __shfl_down_sync(0xffffffffu, s, off);
    __shared__ float rs[8];
    int lane = threadIdx.x & 31, w = threadIdx.x >> 5;
    if (lane == 0) rs[w] = s;
    __syncthreads();
    if (threadIdx.x == 0) {
        float tot = 0.f;
        #pragma unroll
        for (int i = 0; i < 8; i++) tot += rs[i];
        g_denom[t] = tot + 1e-8f;
    }
}

// ---------------- precompute GEMMs (fp32 SIMT, vectorized smem) ----------------
#define PBM 64
#define PBN 64
#define PBK 32
__global__ __launch_bounds__(256) void k_gammah(const float* __restrict__ d_all,
                                                const float* __restrict__ W,
                                                const float* __restrict__ bias) {
    __shared__ float sAT[PBK][PBM + 4];
    __shared__ float sB [PBK][PBN + 4];
    const int rr0 = blockIdx.y * PBM;
    const int bn  = blockIdx.x * PBN;
    const int tid = threadIdx.x;
    const int tr = tid >> 4, tc = tid & 15;
    float acc[4][4] = {};
    for (int k0 = 0; k0 < F_; k0 += PBK) {
        #pragma unroll
        for (int i = tid; i < PBM * PBK; i += 256) {
            int r = i >> 5, kk = i & 31;
            int rr = rr0 + r;
            int b = rr & 255, tt = rr >> 8;
            sAT[kk][r] = d_all[(b * T_ + tt) * F_ + k0 + kk];
        }
        #pragma unroll
        for (int i = tid; i < PBK * PBN; i += 256) {
            int nl = i >> 5, kk = i & 31;
            sB[kk][nl] = W[(bn + nl) * F_ + k0 + kk];
        }
        __syncthreads();
        #pragma unroll
        for (int kk = 0; kk < PBK; kk++) {
            float4 a4 = *(const float4*)&sAT[kk][tr * 4];
            float4 b4 = *(const float4*)&sB[kk][tc * 4];
            const float* a = &a4.x;
            const float* bb = &b4.x;
            #pragma unroll
            for (int i = 0; i < 4; i++)
                #pragma unroll
                for (int j = 0; j < 4; j++) acc[i][j] += a[i] * bb[j];
        }
        __syncthreads();
    }
    #pragma unroll
    for (int i = 0; i < 4; i++) {
        int rr = rr0 + tr * 4 + i;
        #pragma unroll
        for (int j = 0; j < 4; j++) {
            int n = bn + tc * 4 + j;
            float v = acc[i][j] + bias[n];
            g_gammah[(size_t)rr * H_ + n] = expf(-fmaxf(v, 0.f));
        }
    }
}

__global__ __launch_bounds__(256) void k_alpha(const float* __restrict__ d_all,
                                               const float* __restrict__ m_all,
                                               const float* __restrict__ tdx_W,
                                               const float* __restrict__ tdx_b,
                                               const float* __restrict__ wc_W,
                                               const float* __restrict__ wc_b) {
    __shared__ float sAT[PBK][PBM + 4];
    __shared__ float sB [PBK][PBN + 4];
    const int rr0 = blockIdx.y * PBM;
    const int bn  = blockIdx.x * PBN;
    const int tid = threadIdx.x;
    const int tr = tid >> 4, tc = tid & 15;
    float acc[4][4] = {};
    for (int k0 = 0; k0 < 2 * F_; k0 += PBK) {
        #pragma unroll
        for (int i = tid; i < PBM * PBK; i += 256) {
            int r = i >> 5, kk = i & 31;
            int rr = rr0 + r;
            int b = rr & 255, tt = rr >> 8;
            int k = k0 + kk;
            float v;
            if (k < F_) {
                float dv = d_all[(b * T_ + tt) * F_ + k];
                float gv = dv * tdx_W[k * F_ + k] + tdx_b[k];
                v = expf(-fmaxf(gv, 0.f));
            } else {
                v = m_all[(b * T_ + tt) * F_ + (k - F_)];
            }
            sAT[kk][r] = v;
        }
        #pragma unroll
        for (int i = tid; i < PBK * PBN; i += 256) {
            int nl = i >> 5, kk = i & 31;
            sB[kk][nl] = wc_W[(bn + nl) * 2 * F_ + k0 + kk];
        }
        __syncthreads();
        #pragma unroll
        for (int kk = 0; kk < PBK; kk++) {
            float4 a4 = *(const float4*)&sAT[kk][tr * 4];
            float4 b4 = *(const float4*)&sB[kk][tc * 4];
            const float* a = &a4.x;
            const float* bb = &b4.x;
            #pragma unroll
            for (int i = 0; i < 4; i++)
                #pragma unroll
                for (int j = 0; j < 4; j++) acc[i][j] += a[i] * bb[j];
        }
        __syncthreads();
    }
    #pragma unroll
    for (int i = 0; i < 4; i++) {
        int rr = rr0 + tr * 4 + i;
        #pragma unroll
        for (int j = 0; j < 4; j++) {
            int n = bn + tc * 4 + j;
            float s = acc[i][j] + wc_b[n];
            g_alpha[rr * F_ + n] = 1.f / (1.f + expf(-s));
        }
    }
}

// ---------------- distributed-flag grid barrier ----------------
__device__ __forceinline__ void gbar(unsigned target) {
    __syncthreads();
    if (threadIdx.x == 0) {
        __threadfence();
        atomicExch(&g_flags[blockIdx.x * 8], target);
    }
    if (threadIdx.x < GRID_MAIN) {
        const volatile unsigned* fl = (const volatile unsigned*)&g_flags[threadIdx.x * 8];
        while (*fl < target) { __nanosleep(32); }
    }
    __syncthreads();
    __threadfence();
}

// smem byte offsets
#define SM_RED 0                     // 128 B
#define SM_XS  128                   // 2*128 floats = 1024 B
#define SM_A   2048                  // 4 x 8KB A slots (S0..S3)
#define SM_W   (SM_A + 32768)        // weights: WHI 96KB (12 chunks x 8KB) + WLO 96KB
#define SMEM_BYTES (SM_W + 196608)   // 231424

// 64x64x64 fp16 2-term MMA chunk: A single at abase; B hi/lo resident
__device__ __forceinline__ void mma_chunk(unsigned abase, unsigned whi, unsigned wlo,
                                          float acc[4][4], int lane, int wr, int wcl) {
    const int arow = wr * 16 + (lane & 15);
    const int aswz = arow & 7;
    #pragma unroll
    for (int ks = 0; ks < 4; ks++) {
        const int achk = ks * 2 + (lane >> 4);
        const unsigned aoff = (unsigned)(arow * 128 + ((achk ^ aswz) << 4));
        uint32_t A[4];
        ldsm_x4(A, abase + aoff);
        uint32_t Bhi[8], Blo[8];
        #pragma unroll
        for (int pair = 0; pair < 2; pair++) {
            const int brow = wcl * 32 + pair * 16 + ((lane >> 4) << 3) + (lane & 7);
            const int bchk = ks * 2 + ((lane >> 3) & 1);
            const unsigned boff = (unsigned)(brow * 128 + ((bchk ^ (brow & 7)) << 4));
            ldsm_x4(Bhi + pair * 4, whi + boff);
            ldsm_x4(Blo + pair * 4, wlo + boff);
        }
        #pragma unroll
        for (int nb = 0; nb < 4; nb++) {
            mma16816(acc[nb], A, Bhi + nb * 2);
            mma16816(acc[nb], A, Blo + nb * 2);
        }
    }
}

// ---------------- the persistent main kernel ----------------
__global__ __launch_bounds__(THREADS_MAIN, 1) void k_main(
    const float* __restrict__ x_all, const float* __restrict__ m_all,
    const float* __restrict__ tx_all, const float* __restrict__ ev_all,
    const float* __restrict__ hist_b, const float* __restrict__ feat_b,
    float* __restrict__ out) {
    extern __shared__ char smem[];
    const unsigned sm = (unsigned)__cvta_generic_to_shared(smem);
    float* red = (float*)(smem + SM_RED);
    float* xs  = (float*)(smem + SM_XS);
    float* Gs  = (float*)(smem + SM_A + 16384);   // aliases S2,S3 after m-mma done

    const int tid = threadIdx.x;
    const int lane = tid & 31;
    const int wid = tid >> 5;
    const int wr = wid & 3, wcl = wid >> 2;      // warp 16x32 tile in 64x64
    const int bi = blockIdx.x;
    const int rg = bi / 34, ct = bi % 34;        // row-group, col-tile
    const int row0 = rg * 64;
    const bool is_hist = (ct >= 32);
    const int nb0 = is_hist ? (2048 + (ct - 32) * 64) : (ct * 64);
    const unsigned S0 = sm + SM_A, S1 = S0 + 8192u, S2 = S0 + 16384u, S3 = S0 + 24576u;
    const unsigned WHI = sm + SM_W, WLO = sm + SM_W + 98304u;

    // ---- one-time: resident weight load (12 chunks hi + lo) ----
    for (int i = tid; i < 12288; i += THREADS_MAIN) {
        int mat = i / 6144, rem = i - mat * 6144;
        int c = rem >> 9, g = rem & 511, r = g >> 3, p = g & 7;
        unsigned dst = (mat ? WLO : WHI) + (unsigned)(c * 8192 + r * 128 + ((p ^ (r & 7)) << 4));
        const __half* src = (mat ? g_Blo : g_Bhi) + (size_t)(nb0 + r) * 768 + c * 64 + p * 8;
        cpa16(dst, src);
    }
    cp_commit();
    cp_wait0();
    __syncthreads();

    float cstate[4] = {0.f, 0.f, 0.f, 0.f};
    unsigned bar = 0;

    for (int t = 0; t < T_; t++) {
        float acc[4][4] = {};

        // ============ P1: K 256..768, A = hdec (fp16 single), weight chunks 4..11 ============
        {
            for (int i = tid; i < 512; i += THREADS_MAIN) {
                int r = i >> 3, p = i & 7;
                unsigned dst = S0 + (unsigned)(r * 128 + ((p ^ (r & 7)) << 4));
                cpa16(dst, g_hd16 + (row0 + r) * H_ + p * 8);
            }
            cp_commit();
            for (int c = 0; c < 8; c++) {
                cp_wait0();
                __syncthreads();
                if (c < 7) {
                    int k0 = (c + 1) * 64;
                    unsigned bb = ((c + 1) & 1) ? S1 : S0;
                    for (int i = tid; i < 512; i += THREADS_MAIN) {
                        int r = i >> 3, p = i & 7;
                        unsigned dst = bb + (unsigned)(r * 128 + ((p ^ (r & 7)) << 4));
                        cpa16(dst, g_hd16 + (row0 + r) * H_ + k0 + p * 8);
                    }
                    cp_commit();
                }
                mma_chunk((c & 1) ? S1 : S0, WHI + (4 + c) * 8192u, WLO + (4 + c) * 8192u,
                          acc, lane, wr, wcl);
            }
        }

        if (is_hist) {
            // write x_hist (+hist_b) from register acc
            const int r0 = wr * 16 + (lane >> 2);
            const int c0g = wcl * 32 + (lane & 3) * 2;
            #pragma unroll
            for (int nb = 0; nb < 4; nb++) {
                #pragma unroll
                for (int q = 0; q < 4; q++) {
                    int r = r0 + ((q >> 1) << 3);
                    int fc = (ct - 32) * 64 + c0g + nb * 8 + (q & 1);
                    __stcg(&g_xhist[(row0 + r) * F_ + fc], acc[nb][q] + hist_b[fc]);
                }
            }
        } else if (t < T_ - 1) {
            // prestage P2 m-chunks into S2/S3 (P1's last mma read S1 only)
            for (int i = tid; i < 1024; i += THREADS_MAIN) {
                int ch = i >> 9, g = i & 511, r = g >> 3, p = g & 7;
                unsigned dst = (ch ? S3 : S2) + (unsigned)(r * 128 + ((p ^ (r & 7)) << 4));
                cpa16(dst, g_m16 + ((size_t)(row0 + r) * T_ + t) * F_ + ch * 64 + p * 8);
            }
            cp_commit();   // group Gm
        }
        gbar(++bar);

        // ============ chain: rows 2bi, 2bi+1 (CTAs 0..127) ============
        if (bi < 128) {
            const int rr = tid >> 7, f = tid & 127;
            const int prow = bi * 2 + rr;
            float xh = __ldcg(&g_xhist[prow * F_ + f]);
            int base = (prow * T_ + t) * F_ + f;
            float mv = m_all[base], xv = x_all[base];
            xs[rr * 128 + f] = mv * xv + (1.f - mv) * xh;
            __syncthreads();
            float z = feat_b[f];
            const float* xrow = xs + rr * 128;
            #pragma unroll 8
            for (int k = 0; k < 128; k++) z += xrow[k] * g_featT[k * F_ + f];
            float al = g_alpha[((size_t)t * B_ + prow) * F_ + f];
            float ch = al * z + (1.f - al) * xh;
            float cc = mv * xv + (1.f - mv) * ch;
            out[base] = cc;
            __stcg(&g_cc16[prow * F_ + f], __float2half(cc));
            float tg = tx_all[base], evv = ev_all[base];
            float e1 = xh - tg, e2 = z - tg, e3 = ch - tg;
            float l = evv * (e1 * e1 + e2 * e2 + e3 * e3);
            #pragma unroll
            for (int off = 16; off > 0; off >>= 1) l += __shfl_down_sync(0xffffffffu, l, off);
            int ln = tid & 31, w = tid >> 5;
            if (ln == 0) red[w] = l;
            __syncthreads();
            if (tid == 0) {
                float tot = 0.f;
                #pragma unroll
                for (int i = 0; i < 8; i++) tot += red[i];
                atomicAdd(&g_loss, (double)tot / ((double)g_denom[t] * (double)T_));
            }
        }
        if (t == T_ - 1) break;
        gbar(++bar);

        // ============ P2: m2,m3 (prestaged S2/S3), cc0->S0, cc1->S1; then LSTM ============
        if (!is_hist) {
            // stage cc0+cc1 in one group
            for (int i = tid; i < 1024; i += THREADS_MAIN) {
                int ch = i >> 9, g = i & 511, r = g >> 3, p = g & 7;
                unsigned dst = (ch ? S1 : S0) + (unsigned)(r * 128 + ((p ^ (r & 7)) << 4));
                cpa16(dst, g_cc16 + (row0 + r) * F_ + ch * 64 + p * 8);
            }
            cp_commit();   // group Gcc; pending = {Gm, Gcc}
            cp_wait1();    // Gm (m) arrived
            __syncthreads();
            mma_chunk(S2, WHI + 2 * 8192u, WLO + 2 * 8192u, acc, lane, wr, wcl);  // m2
            mma_chunk(S3, WHI + 3 * 8192u, WLO + 3 * 8192u, acc, lane, wr, wcl);  // m3
            cp_wait0();    // Gcc arrived
            __syncthreads();
            mma_chunk(S0, WHI + 0 * 8192u, WLO + 0 * 8192u, acc, lane, wr, wcl);  // cc0
            mma_chunk(S1, WHI + 1 * 8192u, WLO + 1 * 8192u, acc, lane, wr, wcl);  // cc1
            __syncthreads();   // all mma reads done before Gs overwrites S2/S3
            // epilogue: Gs (at S2,S3) = acc + bias
            {
                const int r0 = wr * 16 + (lane >> 2);
                const int c0g = wcl * 32 + (lane & 3) * 2;
                #pragma unroll
                for (int nb = 0; nb < 4; nb++) {
                    #pragma unroll
                    for (int q = 0; q < 4; q++) {
                        int r = r0 + ((q >> 1) << 3);
                        int c = c0g + nb * 8 + (q & 1);
                        Gs[r * 64 + c] = acc[nb][q] + g_biasp[ct * 64 + c];
                    }
                }
            }
            __syncthreads();
            // LSTM on block-exclusive cells (64 rows x 16 j's), c-state in regs
            #pragma unroll
            for (int u = 0; u < 4; u++) {
                int cell = u * 256 + tid;
                int r = cell >> 4, jj = cell & 15;
                float ig = Gs[r * 64 + jj];
                float fg = Gs[r * 64 + 16 + jj];
                float gg = Gs[r * 64 + 32 + jj];
                float og = Gs[r * 64 + 48 + jj];
                float cn = sigf(fg) * cstate[u] + sigf(ig) * tanhf(gg);
                cstate[u] = cn;
                float h = sigf(og) * tanhf(cn);
                int gidx = (row0 + r) * H_ + ct * 16 + jj;
                float hd = h * g_gammah[(size_t)(t + 1) * B_ * H_ + gidx];
                __stcg(&g_hd16[gidx], __float2half(hd));
            }
        }
        gbar(++bar);
    }
}

// ---------------- finalize ----------------
__global__ void k_finish(float* __restrict__ out, int out_size) {
    out[out_size - 1] = (float)g_loss;
}

// ---------------- launch ----------------
extern "C" void kernel_launch(void* const* d_in, const int* in_sizes, int n_in,
                              void* d_out, int out_size) {
    const float* x      = (const float*)d_in[0];
    const float* m      = (const float*)d_in[1];
    const float* d      = (const float*)d_in[2];
    const float* tx     = (const float*)d_in[3];
    const float* ev     = (const float*)d_in[4];
    const float* td_h_W = (const float*)d_in[5];
    const float* td_h_b = (const float*)d_in[6];
    const float* td_x_W = (const float*)d_in[7];
    const float* td_x_b = (const float*)d_in[8];
    const float* hist_W = (const float*)d_in[9];
    const float* hist_b = (const float*)d_in[10];
    const float* feat_W = (const float*)d_in[11];
    const float* feat_b = (const float*)d_in[12];
    const float* wc_W   = (const float*)d_in[13];
    const float* wc_b   = (const float*)d_in[14];
    const float* W_ih   = (const float*)d_in[15];
    const float* W_hh   = (const float*)d_in[16];
    const float* b_ih   = (const float*)d_in[17];
    const float* b_hh   = (const float*)d_in[18];
    float* out = (float*)d_out;

    static int smem_set = 0;
    if (!smem_set) {
        cudaFuncSetAttribute(k_main, cudaFuncAttributeMaxDynamicSharedMemorySize, SMEM_BYTES);
        smem_set = 1;
    }

    k_init<<<512, 256>>>(feat_W);
    k_prep<<<1024, 256>>>(W_ih, W_hh, hist_W, b_ih, b_hh, m);
    k_denom<<<T_, 256>>>(ev);
    k_gammah<<<dim3(H_ / PBN, (T_ * B_) / PBM), 256>>>(d, td_h_W, td_h_b);
    k_alpha<<<dim3(F_ / PBN, (T_ * B_) / PBM), 256>>>(d, m, td_x_W, td_x_b, wc_W, wc_b);
    k_main<<<GRID_MAIN, THREADS_MAIN, SMEM_BYTES>>>(x, m, tx, ev, hist_b, feat_b, out);
    k_finish<<<1, 1>>>(out, out_size);
}